// round 1
// baseline (speedup 1.0000x reference)
#include <cuda_runtime.h>
#include <math.h>

// ---------------- problem constants ----------------
#define BATCH  2
#define TQ     2048
#define CDIM   1024
#define NHEAD  16
#define DHEAD  64
#define C3     (3 * CDIM)
#define BQ     64          // query tile
#define BKV    64          // key tile
#define SPAD   65          // padded stride for transposed/score tiles (conflict-free)
#define NQT    (TQ / BQ)   // 32 query tiles
#define NROWS  (BATCH * NHEAD * TQ)   // 65536 rows for entropy mean

// ---------------- scratch (device globals: alloc-free) ----------------
__device__ float g_qkv [BATCH * TQ * C3];     // [B*T, 3C]  (q|k|v interleaved per row)
__device__ float g_yatt[BATCH * TQ * CDIM];   // [B*T, C]   attention output pre-proj
__device__ float g_ent [BATCH * NHEAD * NQT]; // per-block entropy partial sums (1024)

// =====================================================================
// SGEMM: C[M,N] = A[M,K] @ B[K,N], row-major. BM=128, BN=64, BK=16,
// 256 threads, 8x4 micro-tile. M%128==0, N%64==0, K%16==0 assumed.
// =====================================================================
__global__ __launch_bounds__(256) void sgemm_kernel(
    const float* __restrict__ A, const float* __restrict__ B,
    float* __restrict__ C, int M, int N, int K)
{
    const int BM = 128, BN = 64, BK = 16;
    __shared__ float As[BM][BK + 1];   // +1 pad: conflict-free column reads
    __shared__ float Bs[BK][BN];

    const int tid = threadIdx.x;
    const int tx  = tid & 15;          // 16 col groups of 4
    const int ty  = tid >> 4;          // 16 row groups of 8
    const int bm  = blockIdx.y * BM;
    const int bn  = blockIdx.x * BN;

    float acc[8][4];
#pragma unroll
    for (int i = 0; i < 8; i++)
#pragma unroll
        for (int j = 0; j < 4; j++) acc[i][j] = 0.f;

    for (int k0 = 0; k0 < K; k0 += BK) {
        // load A tile: 128x16 = 512 float4, 2 per thread
#pragma unroll
        for (int it = 0; it < 2; it++) {
            int l  = tid + it * 256;
            int r  = l >> 2;
            int kq = (l & 3) * 4;
            float4 v = *(const float4*)&A[(size_t)(bm + r) * K + k0 + kq];
            As[r][kq + 0] = v.x;
            As[r][kq + 1] = v.y;
            As[r][kq + 2] = v.z;
            As[r][kq + 3] = v.w;
        }
        // load B tile: 16x64 = 256 float4, 1 per thread
        {
            int kk = tid >> 4;
            int j4 = (tid & 15) * 4;
            float4 v = *(const float4*)&B[(size_t)(k0 + kk) * N + bn + j4];
            *(float4*)&Bs[kk][j4] = v;
        }
        __syncthreads();

#pragma unroll
        for (int kk = 0; kk < BK; kk++) {
            float a[8], b[4];
            float4 b4 = *(const float4*)&Bs[kk][tx * 4];
            b[0] = b4.x; b[1] = b4.y; b[2] = b4.z; b[3] = b4.w;
#pragma unroll
            for (int i = 0; i < 8; i++) a[i] = As[ty * 8 + i][kk];
#pragma unroll
            for (int i = 0; i < 8; i++)
#pragma unroll
                for (int j = 0; j < 4; j++)
                    acc[i][j] += a[i] * b[j];
        }
        __syncthreads();
    }

#pragma unroll
    for (int i = 0; i < 8; i++) {
        float4 v = make_float4(acc[i][0], acc[i][1], acc[i][2], acc[i][3]);
        *(float4*)&C[(size_t)(bm + ty * 8 + i) * N + bn + tx * 4] = v;
    }
}

// =====================================================================
// Flash attention (fp32, causal) + online entropy.
// Grid: (NQT, NHEAD, BATCH). Block: 256 threads, 64 queries per block.
// Online state per row: m (max), l (sum exp), A (sum p~*s).
// Entropy per row: H = m + log l - A/l  ==  -sum p log p.
// =====================================================================
extern __shared__ float smem[];

__global__ __launch_bounds__(256) void flash_kernel()
{
    float* sQT = smem;               // [64 d][65] transposed Q
    float* sKT = smem + 4160;        // [64 d][65] transposed K
    float* sV  = smem + 8320;        // [64 key][64 d]
    float* sS  = smem + 12416;       // [64 row][65] scores / probs
    float* sM  = smem + 16576;       // [64] running max
    float* sL  = sM + 64;            // [64] running sumexp
    float* sA  = sM + 128;           // [64] running sum p~*s
    float* sSc = sM + 192;           // [64] rescale factor of this tile

    const int qt  = blockIdx.x;
    const int h   = blockIdx.y;
    const int b   = blockIdx.z;
    const int tid = threadIdx.x;
    const int tx  = tid & 15;        // key / dim groups of 4
    const int ty  = tid >> 4;        // row groups of 4
    const float scale = 0.125f;      // 1/sqrt(64)

    const float* qbase = g_qkv + (size_t)b * TQ * C3 + h * DHEAD;
    const float* kbase = qbase + CDIM;
    const float* vbase = qbase + 2 * CDIM;

    // ---- load Q tile transposed: sQT[d][row] ----
#pragma unroll
    for (int it = 0; it < 4; it++) {
        int l  = tid + it * 256;     // 1024 float4
        int r  = l >> 4;             // row 0..63
        int d4 = (l & 15) * 4;
        float4 v = *(const float4*)&qbase[(size_t)(qt * BQ + r) * C3 + d4];
        sQT[(d4 + 0) * SPAD + r] = v.x;
        sQT[(d4 + 1) * SPAD + r] = v.y;
        sQT[(d4 + 2) * SPAD + r] = v.z;
        sQT[(d4 + 3) * SPAD + r] = v.w;
    }
    if (tid < 64) { sM[tid] = -1e30f; sL[tid] = 0.f; sA[tid] = 0.f; }

    float acc[4][4];
#pragma unroll
    for (int i = 0; i < 4; i++)
#pragma unroll
        for (int j = 0; j < 4; j++) acc[i][j] = 0.f;

    for (int j = 0; j <= qt; j++) {
        __syncthreads();   // protect sKT/sV/sS from previous iteration readers
        // ---- load K (transposed) and V (natural) tiles ----
#pragma unroll
        for (int it = 0; it < 4; it++) {
            int l  = tid + it * 256;
            int r  = l >> 4;
            int d4 = (l & 15) * 4;
            size_t goff = (size_t)(j * BKV + r) * C3 + d4;
            float4 kv = *(const float4*)&kbase[goff];
            sKT[(d4 + 0) * SPAD + r] = kv.x;
            sKT[(d4 + 1) * SPAD + r] = kv.y;
            sKT[(d4 + 2) * SPAD + r] = kv.z;
            sKT[(d4 + 3) * SPAD + r] = kv.w;
            float4 vv = *(const float4*)&vbase[goff];
            *(float4*)&sV[r * 64 + d4] = vv;
        }
        __syncthreads();

        // ---- S = (Q K^T) * scale, causal mask, store to sS ----
        float s[4][4];
#pragma unroll
        for (int i = 0; i < 4; i++)
#pragma unroll
            for (int jj = 0; jj < 4; jj++) s[i][jj] = 0.f;

#pragma unroll 4
        for (int d = 0; d < 64; d++) {
            float a[4], bb[4];
#pragma unroll
            for (int i = 0; i < 4; i++)  a[i]  = sQT[d * SPAD + ty * 4 + i];
#pragma unroll
            for (int jj = 0; jj < 4; jj++) bb[jj] = sKT[d * SPAD + tx * 4 + jj];
#pragma unroll
            for (int i = 0; i < 4; i++)
#pragma unroll
                for (int jj = 0; jj < 4; jj++)
                    s[i][jj] += a[i] * bb[jj];
        }
        const bool diag = (j == qt);
#pragma unroll
        for (int i = 0; i < 4; i++) {
#pragma unroll
            for (int jj = 0; jj < 4; jj++) {
                float val = s[i][jj] * scale;
                if (diag && (tx * 4 + jj) > (ty * 4 + i)) val = -1e30f;
                sS[(ty * 4 + i) * SPAD + tx * 4 + jj] = val;
            }
        }
        __syncthreads();

        // ---- online softmax + entropy update: 4 threads per row ----
        {
            const int row  = tid >> 2;
            const int part = tid & 3;
            float* Srow = sS + row * SPAD + part * 16;
            float mt = -1e30f;
#pragma unroll
            for (int c = 0; c < 16; c++) mt = fmaxf(mt, Srow[c]);
            mt = fmaxf(mt, __shfl_xor_sync(0xffffffffu, mt, 1));
            mt = fmaxf(mt, __shfl_xor_sync(0xffffffffu, mt, 2));
            const float m_old = sM[row];
            const float m_new = fmaxf(m_old, mt);
            float lsum = 0.f, asum = 0.f;
#pragma unroll
            for (int c = 0; c < 16; c++) {
                float sv = Srow[c];
                float p  = __expf(sv - m_new);
                Srow[c]  = p;                  // overwrite with p~
                lsum += p;
                asum += p * sv;
            }
            lsum += __shfl_xor_sync(0xffffffffu, lsum, 1);
            lsum += __shfl_xor_sync(0xffffffffu, lsum, 2);
            asum += __shfl_xor_sync(0xffffffffu, asum, 1);
            asum += __shfl_xor_sync(0xffffffffu, asum, 2);
            if (part == 0) {
                float sc = __expf(m_old - m_new);   // 0 on first tile (m_old=-1e30)
                sL[row] = sL[row] * sc + lsum;
                sA[row] = sA[row] * sc + asum;
                sM[row] = m_new;
                sSc[row] = sc;
            }
        }
        __syncthreads();

        // ---- rescale O, then O += P @ V ----
#pragma unroll
        for (int i = 0; i < 4; i++) {
            float sc = sSc[ty * 4 + i];
#pragma unroll
            for (int jj = 0; jj < 4; jj++) acc[i][jj] *= sc;
        }
#pragma unroll 4
        for (int kk = 0; kk < 64; kk++) {
            float p[4];
#pragma unroll
            for (int i = 0; i < 4; i++) p[i] = sS[(ty * 4 + i) * SPAD + kk];
            float4 v4 = *(const float4*)&sV[kk * 64 + tx * 4];
#pragma unroll
            for (int i = 0; i < 4; i++) {
                acc[i][0] += p[i] * v4.x;
                acc[i][1] += p[i] * v4.y;
                acc[i][2] += p[i] * v4.z;
                acc[i][3] += p[i] * v4.w;
            }
        }
    }
    __syncthreads();

    // ---- write O = acc / l into g_yatt [B*T, C] layout ----
#pragma unroll
    for (int i = 0; i < 4; i++) {
        int row = ty * 4 + i;
        float inv = 1.f / sL[row];
        float4 v = make_float4(acc[i][0] * inv, acc[i][1] * inv,
                               acc[i][2] * inv, acc[i][3] * inv);
        size_t gi = (size_t)(b * TQ + qt * BQ + row) * CDIM + h * DHEAD + tx * 4;
        *(float4*)&g_yatt[gi] = v;
    }

    // ---- per-block entropy partial (deterministic) ----
    if (tid < 64) {
        float l = sL[tid];
        sS[tid] = sM[tid] + __logf(l) - sA[tid] / l;
    }
    __syncthreads();
    if (tid == 0) {
        float t = 0.f;
#pragma unroll 8
        for (int r = 0; r < 64; r++) t += sS[r];
        g_ent[((size_t)b * NHEAD + h) * NQT + qt] = t;
    }
}

// =====================================================================
// Final entropy reduction (deterministic tree) -> d_out[out_size-1]
// =====================================================================
__global__ void ent_final_kernel(float* __restrict__ out, int out_size)
{
    __shared__ float red[256];
    int tid = threadIdx.x;
    float s = 0.f;
    for (int i = tid; i < BATCH * NHEAD * NQT; i += 256) s += g_ent[i];
    red[tid] = s;
    __syncthreads();
    for (int st = 128; st > 0; st >>= 1) {
        if (tid < st) red[tid] += red[tid + st];
        __syncthreads();
    }
    if (tid == 0) out[out_size - 1] = red[0] / (float)NROWS;
}

// =====================================================================
// launch
// =====================================================================
extern "C" void kernel_launch(void* const* d_in, const int* in_sizes, int n_in,
                              void* d_out, int out_size)
{
    const float* x      = (const float*)d_in[0];   // [B,T,C]
    const float* w_attn = (const float*)d_in[1];   // [C, 3C]
    const float* w_proj = (const float*)d_in[2];   // [C, C]
    float* out = (float*)d_out;
    (void)in_sizes; (void)n_in;

    float *qkv_ptr, *yatt_ptr;
    cudaGetSymbolAddress((void**)&qkv_ptr,  g_qkv);
    cudaGetSymbolAddress((void**)&yatt_ptr, g_yatt);

    const int FLASH_SMEM = 16832 * 4;   // 67,328 bytes
    cudaFuncSetAttribute(flash_kernel,
                         cudaFuncAttributeMaxDynamicSharedMemorySize, FLASH_SMEM);

    // 1) qkv = x @ w_attn   (4096 x 3072 x 1024)
    {
        dim3 grid(C3 / 64, (BATCH * TQ) / 128);
        sgemm_kernel<<<grid, 256>>>(x, w_attn, qkv_ptr, BATCH * TQ, C3, CDIM);
    }
    // 2) causal flash attention + entropy partials
    {
        dim3 grid(NQT, NHEAD, BATCH);
        flash_kernel<<<grid, 256, FLASH_SMEM>>>();
    }
    // 3) y = yatt @ w_proj  (4096 x 1024 x 1024) -> d_out
    {
        dim3 grid(CDIM / 64, (BATCH * TQ) / 128);
        sgemm_kernel<<<grid, 256>>>(yatt_ptr, w_proj, out, BATCH * TQ, CDIM, CDIM);
    }
    // 4) entropy scalar -> d_out[out_size-1]
    ent_final_kernel<<<1, 256>>>(out, out_size);
}

// round 2
// speedup vs baseline: 1.2768x; 1.2768x over previous
#include <cuda_runtime.h>
#include <math.h>

// ---------------- problem constants ----------------
#define BATCH  2
#define TQ     2048
#define CDIM   1024
#define NHEAD  16
#define DHEAD  64
#define C3     (3 * CDIM)
#define NQT2   (TQ / 128)            // 16 query tiles of 128 rows
#define NROWS  (BATCH * NHEAD * TQ)  // 65536

// ---------------- scratch (device globals: alloc-free) ----------------
__device__ float g_qkv [BATCH * TQ * C3];
__device__ float g_yatt[BATCH * TQ * CDIM];
__device__ float g_ent [BATCH * NHEAD * NQT2];   // 512 partials

// ---------------- tf32 helpers ----------------
__device__ __forceinline__ unsigned f2tf(float x) {
    unsigned u; asm("cvt.rna.tf32.f32 %0, %1;" : "=r"(u) : "f"(x)); return u;
}
__device__ __forceinline__ void split_tf(float x, unsigned& hi, unsigned& lo) {
    hi = f2tf(x);
    lo = f2tf(x - __uint_as_float(hi));
}
__device__ __forceinline__ void mma8(float* c, const unsigned* a, const unsigned* b) {
    asm volatile(
        "mma.sync.aligned.m16n8k8.row.col.f32.tf32.tf32.f32 "
        "{%0,%1,%2,%3},{%4,%5,%6,%7},{%8,%9},{%0,%1,%2,%3};"
        : "+f"(c[0]), "+f"(c[1]), "+f"(c[2]), "+f"(c[3])
        : "r"(a[0]), "r"(a[1]), "r"(a[2]), "r"(a[3]), "r"(b[0]), "r"(b[1]));
}

// =====================================================================
// GEMM (tf32x3): C[M,N] = A[M,K] @ B[K,N] row-major.
// Block 128x128, BK=16, 256 threads, warp grid 4(m) x 2(n), warp 32x64.
// =====================================================================
#define GAPAD 20
#define GBPAD 136
__global__ __launch_bounds__(256) void gemm_tf32x3(
    const float* __restrict__ A, const float* __restrict__ B,
    float* __restrict__ C, int M, int N, int K)
{
    __shared__ float As[2][128][GAPAD];   // [row][k]
    __shared__ float Bs[2][16][GBPAD];    // [k][n]

    const int tid  = threadIdx.x;
    const int lane = tid & 31, wid = tid >> 5;
    const int g = lane >> 2, t = lane & 3;
    const int wm = wid & 3, wn = wid >> 2;
    const int bm = blockIdx.y * 128, bn = blockIdx.x * 128;

    const int ar  = tid >> 2;         // A rows: ar, ar+64
    const int ak4 = (tid & 3) * 4;
    const int bk0 = tid >> 5;         // B k rows: bk0, bk0+8
    const int bn4 = (tid & 31) * 4;

    float c[2][8][4];
#pragma unroll
    for (int mt = 0; mt < 2; mt++)
#pragma unroll
        for (int nt = 0; nt < 8; nt++)
#pragma unroll
            for (int i = 0; i < 4; i++) c[mt][nt][i] = 0.f;

    const int nIter = K / 16;
    float4 pa0, pa1, pb0, pb1;

    // prologue: tile 0
    pa0 = *(const float4*)&A[(size_t)(bm + ar) * K + ak4];
    pa1 = *(const float4*)&A[(size_t)(bm + ar + 64) * K + ak4];
    pb0 = *(const float4*)&B[(size_t)(bk0) * N + bn + bn4];
    pb1 = *(const float4*)&B[(size_t)(bk0 + 8) * N + bn + bn4];
    *(float4*)&As[0][ar][ak4]      = pa0;
    *(float4*)&As[0][ar + 64][ak4] = pa1;
    *(float4*)&Bs[0][bk0][bn4]     = pb0;
    *(float4*)&Bs[0][bk0 + 8][bn4] = pb1;
    __syncthreads();

    for (int it = 0; it < nIter; it++) {
        const int buf = it & 1;
        if (it + 1 < nIter) {
            const int k0 = (it + 1) * 16;
            pa0 = *(const float4*)&A[(size_t)(bm + ar) * K + k0 + ak4];
            pa1 = *(const float4*)&A[(size_t)(bm + ar + 64) * K + k0 + ak4];
            pb0 = *(const float4*)&B[(size_t)(k0 + bk0) * N + bn + bn4];
            pb1 = *(const float4*)&B[(size_t)(k0 + bk0 + 8) * N + bn + bn4];
        }
#pragma unroll
        for (int ks = 0; ks < 2; ks++) {
            unsigned ah[2][4], al[2][4];
#pragma unroll
            for (int mt = 0; mt < 2; mt++) {
                const int mb = wm * 32 + mt * 16;
                split_tf(As[buf][mb + g][8 * ks + t],         ah[mt][0], al[mt][0]);
                split_tf(As[buf][mb + g + 8][8 * ks + t],     ah[mt][1], al[mt][1]);
                split_tf(As[buf][mb + g][8 * ks + t + 4],     ah[mt][2], al[mt][2]);
                split_tf(As[buf][mb + g + 8][8 * ks + t + 4], ah[mt][3], al[mt][3]);
            }
#pragma unroll
            for (int nt = 0; nt < 8; nt++) {
                const int nb = wn * 64 + nt * 8;
                unsigned bh[2], bl[2];
                split_tf(Bs[buf][8 * ks + t][nb + g],     bh[0], bl[0]);
                split_tf(Bs[buf][8 * ks + t + 4][nb + g], bh[1], bl[1]);
#pragma unroll
                for (int mt = 0; mt < 2; mt++) {
                    mma8(c[mt][nt], ah[mt], bh);
                    mma8(c[mt][nt], al[mt], bh);
                    mma8(c[mt][nt], ah[mt], bl);
                }
            }
        }
        if (it + 1 < nIter) {
            const int nb = buf ^ 1;
            *(float4*)&As[nb][ar][ak4]      = pa0;
            *(float4*)&As[nb][ar + 64][ak4] = pa1;
            *(float4*)&Bs[nb][bk0][bn4]     = pb0;
            *(float4*)&Bs[nb][bk0 + 8][bn4] = pb1;
        }
        __syncthreads();
    }

#pragma unroll
    for (int mt = 0; mt < 2; mt++) {
#pragma unroll
        for (int nt = 0; nt < 8; nt++) {
            const int row = bm + wm * 32 + mt * 16 + g;
            const int col = bn + wn * 64 + nt * 8 + 2 * t;
            float2 v0 = make_float2(c[mt][nt][0], c[mt][nt][1]);
            float2 v1 = make_float2(c[mt][nt][2], c[mt][nt][3]);
            *(float2*)&C[(size_t)row * N + col]       = v0;
            *(float2*)&C[(size_t)(row + 8) * N + col] = v1;
        }
    }
}

// =====================================================================
// Flash attention (tf32x3 mma, causal) + online entropy.
// Grid (NQT2, NHEAD, BATCH). 256 threads = 8 warps, Q tile 128 rows,
// warp owns 16 rows x 64 keys. KV tile = 64.
// =====================================================================
extern __shared__ float fsm[];

__global__ __launch_bounds__(256) void flash_tf32()
{
    float* sQ   = fsm;                 // [128][72]
    float* sK   = fsm + 128 * 72;      // [64][72]
    float* sV   = sK + 64 * 72;        // [64][72]
    float* sred = sV + 64 * 72;        // [64]

    const int qt = blockIdx.x, h = blockIdx.y, b = blockIdx.z;
    const int tid = threadIdx.x, lane = tid & 31, wid = tid >> 5;
    const int g = lane >> 2, t = lane & 3;

    const float* qbase = g_qkv + (size_t)b * TQ * C3 + h * DHEAD;
    const float* kbase = qbase + CDIM;
    const float* vbase = qbase + 2 * CDIM;

    // load Q tile [128][64] -> sQ
#pragma unroll
    for (int it = 0; it < 8; it++) {
        int l = tid + it * 256;
        int r = l >> 4, d4 = (l & 15) * 4;
        float4 v = *(const float4*)&qbase[(size_t)(qt * 128 + r) * C3 + d4];
        *(float4*)&sQ[r * 72 + d4] = v;
    }

    float oc[8][4];
#pragma unroll
    for (int nt = 0; nt < 8; nt++)
#pragma unroll
        for (int i = 0; i < 4; i++) oc[nt][i] = 0.f;

    float m0 = -1e30f, m1 = -1e30f, l0 = 0.f, l1 = 0.f, aa0 = 0.f, aa1 = 0.f;
    const int rowbase = qt * 128 + wid * 16;
    const int nj = 2 * qt + 2;

    for (int j = 0; j < nj; j++) {
        __syncthreads();
#pragma unroll
        for (int it = 0; it < 4; it++) {
            int l = tid + it * 256;
            int r = l >> 4, d4 = (l & 15) * 4;
            size_t goff = (size_t)(j * 64 + r) * C3 + d4;
            *(float4*)&sK[r * 72 + d4] = *(const float4*)&kbase[goff];
            *(float4*)&sV[r * 72 + d4] = *(const float4*)&vbase[goff];
        }
        __syncthreads();

        // ---- S = Q K^T (tf32x3) ----
        float sc[8][4];
#pragma unroll
        for (int nt = 0; nt < 8; nt++)
#pragma unroll
            for (int i = 0; i < 4; i++) sc[nt][i] = 0.f;

#pragma unroll
        for (int ks = 0; ks < 8; ks++) {
            unsigned ah[4], al[4];
            split_tf(sQ[(wid * 16 + g) * 72 + 8 * ks + t],         ah[0], al[0]);
            split_tf(sQ[(wid * 16 + g + 8) * 72 + 8 * ks + t],     ah[1], al[1]);
            split_tf(sQ[(wid * 16 + g) * 72 + 8 * ks + t + 4],     ah[2], al[2]);
            split_tf(sQ[(wid * 16 + g + 8) * 72 + 8 * ks + t + 4], ah[3], al[3]);
#pragma unroll
            for (int nt = 0; nt < 8; nt++) {
                unsigned bh[2], bl[2];
                split_tf(sK[(nt * 8 + g) * 72 + 8 * ks + t],     bh[0], bl[0]);
                split_tf(sK[(nt * 8 + g) * 72 + 8 * ks + t + 4], bh[1], bl[1]);
                mma8(sc[nt], ah, bh);
                mma8(sc[nt], al, bh);
                mma8(sc[nt], ah, bl);
            }
        }

        // ---- scale + causal mask ----
        const bool needmask = (j * 64 + 63) > rowbase;
#pragma unroll
        for (int nt = 0; nt < 8; nt++) {
#pragma unroll
            for (int cc = 0; cc < 4; cc++) {
                float v = sc[nt][cc] * 0.125f;
                if (needmask) {
                    int col = j * 64 + nt * 8 + 2 * t + (cc & 1);
                    int row = rowbase + g + ((cc >> 1) << 3);
                    if (col > row) v = -1e30f;
                }
                sc[nt][cc] = v;
            }
        }

        // ---- online softmax + entropy (rows g and g+8) ----
        float mt0 = -1e30f, mt1 = -1e30f;
#pragma unroll
        for (int nt = 0; nt < 8; nt++) {
            mt0 = fmaxf(mt0, fmaxf(sc[nt][0], sc[nt][1]));
            mt1 = fmaxf(mt1, fmaxf(sc[nt][2], sc[nt][3]));
        }
        mt0 = fmaxf(mt0, __shfl_xor_sync(0xffffffffu, mt0, 1));
        mt0 = fmaxf(mt0, __shfl_xor_sync(0xffffffffu, mt0, 2));
        mt1 = fmaxf(mt1, __shfl_xor_sync(0xffffffffu, mt1, 1));
        mt1 = fmaxf(mt1, __shfl_xor_sync(0xffffffffu, mt1, 2));

        const float mn0 = fmaxf(m0, mt0), mn1 = fmaxf(m1, mt1);
        const float ex0 = __expf(m0 - mn0), ex1 = __expf(m1 - mn1);

        float ls0 = 0.f, ls1 = 0.f, as0 = 0.f, as1 = 0.f;
#pragma unroll
        for (int nt = 0; nt < 8; nt++) {
            float s0 = sc[nt][0], s1 = sc[nt][1];
            float s2 = sc[nt][2], s3 = sc[nt][3];
            float p0 = __expf(s0 - mn0), p1 = __expf(s1 - mn0);
            float p2 = __expf(s2 - mn1), p3 = __expf(s3 - mn1);
            sc[nt][0] = p0; sc[nt][1] = p1; sc[nt][2] = p2; sc[nt][3] = p3;
            ls0 += p0 + p1;           ls1 += p2 + p3;
            as0 += p0 * s0 + p1 * s1; as1 += p2 * s2 + p3 * s3;
        }
        ls0 += __shfl_xor_sync(0xffffffffu, ls0, 1);
        ls0 += __shfl_xor_sync(0xffffffffu, ls0, 2);
        ls1 += __shfl_xor_sync(0xffffffffu, ls1, 1);
        ls1 += __shfl_xor_sync(0xffffffffu, ls1, 2);
        as0 += __shfl_xor_sync(0xffffffffu, as0, 1);
        as0 += __shfl_xor_sync(0xffffffffu, as0, 2);
        as1 += __shfl_xor_sync(0xffffffffu, as1, 1);
        as1 += __shfl_xor_sync(0xffffffffu, as1, 2);

        l0 = l0 * ex0 + ls0;  aa0 = aa0 * ex0 + as0;  m0 = mn0;
        l1 = l1 * ex1 + ls1;  aa1 = aa1 * ex1 + as1;  m1 = mn1;

        // rescale O
#pragma unroll
        for (int nt = 0; nt < 8; nt++) {
            oc[nt][0] *= ex0; oc[nt][1] *= ex0;
            oc[nt][2] *= ex1; oc[nt][3] *= ex1;
        }

        // ---- O += P @ V  (P via register shuffle C-layout -> A-layout) ----
#pragma unroll
        for (int ks = 0; ks < 8; ks++) {
            const int srcA = (lane & ~3) | (t >> 1);
            const int srcB = srcA + 2;
            float x0 = __shfl_sync(0xffffffffu, sc[ks][0], srcA);
            float x1 = __shfl_sync(0xffffffffu, sc[ks][1], srcA);
            float y0 = __shfl_sync(0xffffffffu, sc[ks][2], srcA);
            float y1 = __shfl_sync(0xffffffffu, sc[ks][3], srcA);
            float z0 = __shfl_sync(0xffffffffu, sc[ks][0], srcB);
            float z1 = __shfl_sync(0xffffffffu, sc[ks][1], srcB);
            float w0 = __shfl_sync(0xffffffffu, sc[ks][2], srcB);
            float w1 = __shfl_sync(0xffffffffu, sc[ks][3], srcB);
            const bool odd = (t & 1);
            float pa0 = odd ? x1 : x0;   // P[g][8ks+t]
            float pa1 = odd ? y1 : y0;   // P[g+8][8ks+t]
            float pa2 = odd ? z1 : z0;   // P[g][8ks+t+4]
            float pa3 = odd ? w1 : w0;   // P[g+8][8ks+t+4]
            unsigned ah[4], al[4];
            split_tf(pa0, ah[0], al[0]);
            split_tf(pa1, ah[1], al[1]);
            split_tf(pa2, ah[2], al[2]);
            split_tf(pa3, ah[3], al[3]);
#pragma unroll
            for (int nt = 0; nt < 8; nt++) {
                unsigned bh[2], bl[2];
                split_tf(sV[(8 * ks + t) * 72 + nt * 8 + g],     bh[0], bl[0]);
                split_tf(sV[(8 * ks + t + 4) * 72 + nt * 8 + g], bh[1], bl[1]);
                mma8(oc[nt], ah, bh);
                mma8(oc[nt], al, bh);
                mma8(oc[nt], ah, bl);
            }
        }
    }

    // ---- write O / l ----
    const float inv0 = 1.f / l0, inv1 = 1.f / l1;
    const int row0 = rowbase + g;
#pragma unroll
    for (int nt = 0; nt < 8; nt++) {
        const int col = h * DHEAD + nt * 8 + 2 * t;
        size_t gi = ((size_t)b * TQ + row0) * CDIM + col;
        float2 v0 = make_float2(oc[nt][0] * inv0, oc[nt][1] * inv0);
        float2 v1 = make_float2(oc[nt][2] * inv1, oc[nt][3] * inv1);
        *(float2*)&g_yatt[gi]            = v0;
        *(float2*)&g_yatt[gi + 8 * CDIM] = v1;
    }

    // ---- entropy partial ----
    if (t == 0) {
        float H = (m0 + __logf(l0) - aa0 / l0) + (m1 + __logf(l1) - aa1 / l1);
        sred[wid * 8 + g] = H;
    }
    __syncthreads();
    if (tid == 0) {
        float s = 0.f;
#pragma unroll 8
        for (int r = 0; r < 64; r++) s += sred[r];
        g_ent[((size_t)b * NHEAD + h) * NQT2 + qt] = s;
    }
}

// =====================================================================
// Final entropy reduction -> d_out[out_size-1]
// =====================================================================
__global__ void ent_final_kernel(float* __restrict__ out, int out_size)
{
    __shared__ float red[256];
    int tid = threadIdx.x;
    float s = 0.f;
    for (int i = tid; i < BATCH * NHEAD * NQT2; i += 256) s += g_ent[i];
    red[tid] = s;
    __syncthreads();
    for (int st = 128; st > 0; st >>= 1) {
        if (tid < st) red[tid] += red[tid + st];
        __syncthreads();
    }
    if (tid == 0) out[out_size - 1] = red[0] / (float)NROWS;
}

// =====================================================================
// launch
// =====================================================================
extern "C" void kernel_launch(void* const* d_in, const int* in_sizes, int n_in,
                              void* d_out, int out_size)
{
    const float* x      = (const float*)d_in[0];
    const float* w_attn = (const float*)d_in[1];
    const float* w_proj = (const float*)d_in[2];
    float* out = (float*)d_out;
    (void)in_sizes; (void)n_in;

    float *qkv_ptr, *yatt_ptr;
    cudaGetSymbolAddress((void**)&qkv_ptr,  g_qkv);
    cudaGetSymbolAddress((void**)&yatt_ptr, g_yatt);

    const int FLASH_SMEM = (128 * 72 + 2 * 64 * 72 + 64) * 4;   // 73,984 B
    cudaFuncSetAttribute(flash_tf32,
                         cudaFuncAttributeMaxDynamicSharedMemorySize, FLASH_SMEM);

    // 1) qkv = x @ w_attn   (4096 x 3072 x 1024)
    {
        dim3 grid(C3 / 128, (BATCH * TQ) / 128);
        gemm_tf32x3<<<grid, 256>>>(x, w_attn, qkv_ptr, BATCH * TQ, C3, CDIM);
    }
    // 2) causal flash attention + entropy partials
    {
        dim3 grid(NQT2, NHEAD, BATCH);
        flash_tf32<<<grid, 256, FLASH_SMEM>>>();
    }
    // 3) y = yatt @ w_proj  (4096 x 1024 x 1024) -> d_out
    {
        dim3 grid(CDIM / 128, (BATCH * TQ) / 128);
        gemm_tf32x3<<<grid, 256>>>(yatt_ptr, w_proj, out, BATCH * TQ, CDIM, CDIM);
    }
    // 4) entropy scalar -> d_out[out_size-1]
    ent_final_kernel<<<1, 256>>>(out, out_size);
}

// round 4
// speedup vs baseline: 1.9714x; 1.5440x over previous
#include <cuda_runtime.h>
#include <cuda_bf16.h>
#include <math.h>
#include <stdint.h>

// ---------------- problem constants ----------------
#define BATCH  2
#define TQ     2048
#define CDIM   1024
#define NHEAD  16
#define DHEAD  64
#define C3     (3 * CDIM)
#define NQT2   (TQ / 128)
#define NROWS  (BATCH * NHEAD * TQ)

// ---------------- scratch ----------------
__device__ float g_qkv [BATCH * TQ * C3];
__device__ float g_yatt[BATCH * TQ * CDIM];
__device__ float g_ent [BATCH * NHEAD * NQT2];

// ---------------- bf16 split helpers ----------------
// Pack (a,b) -> bf16x2 hi word + bf16x2 lo (residual) word.
__device__ __forceinline__ void split2(float a, float b, unsigned& hi, unsigned& lo) {
    __nv_bfloat162 h = __floats2bfloat162_rn(a, b);
    float ra = a - __bfloat162float(h.x);
    float rb = b - __bfloat162float(h.y);
    __nv_bfloat162 l = __floats2bfloat162_rn(ra, rb);
    hi = *reinterpret_cast<unsigned*>(&h);
    lo = *reinterpret_cast<unsigned*>(&l);
}
// m16n8k16 bf16 mma, fp32 accumulate
__device__ __forceinline__ void mma16(float* c, const unsigned* a, const unsigned* b) {
    asm volatile(
        "mma.sync.aligned.m16n8k16.row.col.f32.bf16.bf16.f32 "
        "{%0,%1,%2,%3},{%4,%5,%6,%7},{%8,%9},{%0,%1,%2,%3};"
        : "+f"(c[0]), "+f"(c[1]), "+f"(c[2]), "+f"(c[3])
        : "r"(a[0]), "r"(a[1]), "r"(a[2]), "r"(a[3]), "r"(b[0]), "r"(b[1]));
}

extern __shared__ unsigned dynsmem[];

// =====================================================================
// GEMM (bf16x3): C[M,N] = A[M,K] @ B[K,N] row-major.
// Block 128x128, BK=32, 256 threads, warps 4(m)x2(n), warp 32x64.
// smem: pre-split hi/lo planes; A [row][k-pair], B^T [n][k-pair].
// =====================================================================
#define GSW   17            // words per plane row (16 pairs + 1 pad)
#define GPLN  (128 * GSW)   // 2176 words per plane
#define GSTG  (4 * GPLN)    // Ahi, Alo, Bhi, Blo

__global__ __launch_bounds__(256) void gemm_bf3(
    const float* __restrict__ A, const float* __restrict__ B,
    float* __restrict__ C, int M, int N, int K)
{
    const int tid = threadIdx.x;
    const int lane = tid & 31, wid = tid >> 5;
    const int g = lane >> 2, t = lane & 3;
    const int wm = wid & 3, wn = wid >> 2;
    const int bm = blockIdx.y * 128, bn = blockIdx.x * 128;

    float c[2][8][4];
#pragma unroll
    for (int mt = 0; mt < 2; mt++)
#pragma unroll
        for (int nt = 0; nt < 8; nt++)
#pragma unroll
            for (int i = 0; i < 4; i++) c[mt][nt][i] = 0.f;

    const int NCH = K / 32;
    float4 ra[4];
    float2 rb0[4], rb1[4];

    // ---- prologue: load + split + store chunk 0 ----
    {
        unsigned* Ah = dynsmem;
        unsigned* Al = Ah + GPLN;
        unsigned* Bh = Al + GPLN;
        unsigned* Bl = Bh + GPLN;
#pragma unroll
        for (int it = 0; it < 4; it++) {
            int idx = tid + it * 256;
            int r = idx >> 3, c4 = idx & 7;
            float4 v = *(const float4*)&A[(size_t)(bm + r) * K + c4 * 4];
            unsigned h0, l0, h1, l1;
            split2(v.x, v.y, h0, l0); split2(v.z, v.w, h1, l1);
            Ah[r * GSW + c4 * 2] = h0; Ah[r * GSW + c4 * 2 + 1] = h1;
            Al[r * GSW + c4 * 2] = l0; Al[r * GSW + c4 * 2 + 1] = l1;
        }
#pragma unroll
        for (int it = 0; it < 4; it++) {
            int idx = tid + it * 256;
            int n2 = idx & 63, k2 = idx >> 6;
            float2 u = *(const float2*)&B[(size_t)(2 * k2) * N + bn + 2 * n2];
            float2 w = *(const float2*)&B[(size_t)(2 * k2 + 1) * N + bn + 2 * n2];
            unsigned h0, l0, h1, l1;
            split2(u.x, w.x, h0, l0); split2(u.y, w.y, h1, l1);
            Bh[(2 * n2) * GSW + k2] = h0; Bh[(2 * n2 + 1) * GSW + k2] = h1;
            Bl[(2 * n2) * GSW + k2] = l0; Bl[(2 * n2 + 1) * GSW + k2] = l1;
        }
    }
    __syncthreads();

    for (int ch = 0; ch < NCH; ch++) {
        const int buf = ch & 1;
        unsigned* Ah = dynsmem + buf * GSTG;
        unsigned* Al = Ah + GPLN;
        unsigned* Bh = Al + GPLN;
        unsigned* Bl = Bh + GPLN;

        // prefetch next chunk into regs
        if (ch + 1 < NCH) {
            const int k0 = (ch + 1) * 32;
#pragma unroll
            for (int it = 0; it < 4; it++) {
                int idx = tid + it * 256;
                int r = idx >> 3, c4 = idx & 7;
                ra[it] = *(const float4*)&A[(size_t)(bm + r) * K + k0 + c4 * 4];
            }
#pragma unroll
            for (int it = 0; it < 4; it++) {
                int idx = tid + it * 256;
                int n2 = idx & 63, k2 = idx >> 6;
                rb0[it] = *(const float2*)&B[(size_t)(k0 + 2 * k2) * N + bn + 2 * n2];
                rb1[it] = *(const float2*)&B[(size_t)(k0 + 2 * k2 + 1) * N + bn + 2 * n2];
            }
        }

        // ---- compute on buf ----
#pragma unroll
        for (int ks = 0; ks < 2; ks++) {
            unsigned ah[2][4], al[2][4];
#pragma unroll
            for (int mt = 0; mt < 2; mt++) {
                const int rb = wm * 32 + mt * 16;
                ah[mt][0] = Ah[(rb + g) * GSW + 8 * ks + t];
                ah[mt][1] = Ah[(rb + g + 8) * GSW + 8 * ks + t];
                ah[mt][2] = Ah[(rb + g) * GSW + 8 * ks + t + 4];
                ah[mt][3] = Ah[(rb + g + 8) * GSW + 8 * ks + t + 4];
                al[mt][0] = Al[(rb + g) * GSW + 8 * ks + t];
                al[mt][1] = Al[(rb + g + 8) * GSW + 8 * ks + t];
                al[mt][2] = Al[(rb + g) * GSW + 8 * ks + t + 4];
                al[mt][3] = Al[(rb + g + 8) * GSW + 8 * ks + t + 4];
            }
#pragma unroll
            for (int nt = 0; nt < 8; nt++) {
                const int n = wn * 64 + nt * 8 + g;
                unsigned bh[2], bl[2];
                bh[0] = Bh[n * GSW + 8 * ks + t];
                bh[1] = Bh[n * GSW + 8 * ks + t + 4];
                bl[0] = Bl[n * GSW + 8 * ks + t];
                bl[1] = Bl[n * GSW + 8 * ks + t + 4];
#pragma unroll
                for (int mt = 0; mt < 2; mt++) {
                    mma16(c[mt][nt], ah[mt], bh);
                    mma16(c[mt][nt], al[mt], bh);
                    mma16(c[mt][nt], ah[mt], bl);
                }
            }
        }

        // split + store prefetched chunk into other buffer
        if (ch + 1 < NCH) {
            unsigned* nAh = dynsmem + (buf ^ 1) * GSTG;
            unsigned* nAl = nAh + GPLN;
            unsigned* nBh = nAl + GPLN;
            unsigned* nBl = nBh + GPLN;
#pragma unroll
            for (int it = 0; it < 4; it++) {
                int idx = tid + it * 256;
                int r = idx >> 3, c4 = idx & 7;
                unsigned h0, l0, h1, l1;
                split2(ra[it].x, ra[it].y, h0, l0);
                split2(ra[it].z, ra[it].w, h1, l1);
                nAh[r * GSW + c4 * 2] = h0; nAh[r * GSW + c4 * 2 + 1] = h1;
                nAl[r * GSW + c4 * 2] = l0; nAl[r * GSW + c4 * 2 + 1] = l1;
            }
#pragma unroll
            for (int it = 0; it < 4; it++) {
                int idx = tid + it * 256;
                int n2 = idx & 63, k2 = idx >> 6;
                unsigned h0, l0, h1, l1;
                split2(rb0[it].x, rb1[it].x, h0, l0);
                split2(rb0[it].y, rb1[it].y, h1, l1);
                nBh[(2 * n2) * GSW + k2] = h0; nBh[(2 * n2 + 1) * GSW + k2] = h1;
                nBl[(2 * n2) * GSW + k2] = l0; nBl[(2 * n2 + 1) * GSW + k2] = l1;
            }
        }
        __syncthreads();
    }

    // ---- epilogue ----
#pragma unroll
    for (int mt = 0; mt < 2; mt++) {
#pragma unroll
        for (int nt = 0; nt < 8; nt++) {
            const int row = bm + wm * 32 + mt * 16 + g;
            const int col = bn + wn * 64 + nt * 8 + 2 * t;
            float2 v0 = make_float2(c[mt][nt][0], c[mt][nt][1]);
            float2 v1 = make_float2(c[mt][nt][2], c[mt][nt][3]);
            *(float2*)&C[(size_t)row * N + col]       = v0;
            *(float2*)&C[(size_t)(row + 8) * N + col] = v1;
        }
    }
}

// =====================================================================
// Flash attention (bf16x3 mma, causal) + online entropy.
// Grid (NQT2, NHEAD, BATCH). 256 threads = 8 warps, warp: 16 rows x 64 keys.
// smem: pre-split hi/lo planes. Q [row][d-pair] s36, K [key][d-pair] s36,
// V^T [d][key-pair] s33.
// =====================================================================
#define QSW 36
#define KSW 36
#define VSW 33
#define OFF_QH 0
#define OFF_QL (OFF_QH + 128 * QSW)
#define OFF_KH (OFF_QL + 128 * QSW)
#define OFF_KL (OFF_KH + 64 * KSW)
#define OFF_VH (OFF_KL + 64 * KSW)
#define OFF_VL (OFF_VH + 64 * VSW)
#define OFF_RED (OFF_VL + 64 * VSW)
#define FLASH_WORDS (OFF_RED + 64)

__global__ __launch_bounds__(256) void flash_bf3()
{
    unsigned* QH = dynsmem + OFF_QH;
    unsigned* QL = dynsmem + OFF_QL;
    unsigned* KH = dynsmem + OFF_KH;
    unsigned* KL = dynsmem + OFF_KL;
    unsigned* VH = dynsmem + OFF_VH;
    unsigned* VL = dynsmem + OFF_VL;
    float* sred  = (float*)(dynsmem + OFF_RED);

    const int qt = blockIdx.x, h = blockIdx.y, b = blockIdx.z;
    const int tid = threadIdx.x, lane = tid & 31, wid = tid >> 5;
    const int g = lane >> 2, t = lane & 3;

    const float* qbase = g_qkv + (size_t)b * TQ * C3 + h * DHEAD;
    const float* kbase = qbase + CDIM;
    const float* vbase = qbase + 2 * CDIM;

    // ---- Q prologue: split into hi/lo planes ----
#pragma unroll
    for (int it = 0; it < 8; it++) {
        int idx = tid + it * 256;
        int r = idx >> 4, d4 = idx & 15;
        float4 v = *(const float4*)&qbase[(size_t)(qt * 128 + r) * C3 + d4 * 4];
        unsigned h0, l0, h1, l1;
        split2(v.x, v.y, h0, l0); split2(v.z, v.w, h1, l1);
        QH[r * QSW + d4 * 2] = h0; QH[r * QSW + d4 * 2 + 1] = h1;
        QL[r * QSW + d4 * 2] = l0; QL[r * QSW + d4 * 2 + 1] = l1;
    }

    float oc[8][4];
#pragma unroll
    for (int nt = 0; nt < 8; nt++)
#pragma unroll
        for (int i = 0; i < 4; i++) oc[nt][i] = 0.f;

    float m0 = -1e30f, m1 = -1e30f, l0s = 0.f, l1s = 0.f, aa0 = 0.f, aa1 = 0.f;
    const int rowbase = qt * 128 + wid * 16;
    const int nj = 2 * qt + 2;

    for (int j = 0; j < nj; j++) {
        __syncthreads();
        // ---- K tile: [64 key][64 d] -> hi/lo pair planes ----
#pragma unroll
        for (int it = 0; it < 4; it++) {
            int idx = tid + it * 256;
            int r = idx >> 4, d4 = idx & 15;
            float4 v = *(const float4*)&kbase[(size_t)(j * 64 + r) * C3 + d4 * 4];
            unsigned h0, l0, h1, l1;
            split2(v.x, v.y, h0, l0); split2(v.z, v.w, h1, l1);
            KH[r * KSW + d4 * 2] = h0; KH[r * KSW + d4 * 2 + 1] = h1;
            KL[r * KSW + d4 * 2] = l0; KL[r * KSW + d4 * 2 + 1] = l1;
        }
        // ---- V tile transposed: VT[d][key pair] ----
#pragma unroll
        for (int it = 0; it < 4; it++) {
            int idx = tid + it * 256;
            int d2 = idx & 31, k2 = idx >> 5;
            float2 u = *(const float2*)&vbase[(size_t)(j * 64 + 2 * k2) * C3 + 2 * d2];
            float2 w = *(const float2*)&vbase[(size_t)(j * 64 + 2 * k2 + 1) * C3 + 2 * d2];
            unsigned h0, l0, h1, l1;
            split2(u.x, w.x, h0, l0);   // d = 2*d2
            split2(u.y, w.y, h1, l1);   // d = 2*d2+1
            VH[(2 * d2) * VSW + k2] = h0; VH[(2 * d2 + 1) * VSW + k2] = h1;
            VL[(2 * d2) * VSW + k2] = l0; VL[(2 * d2 + 1) * VSW + k2] = l1;
        }
        __syncthreads();

        // ---- S = Q K^T (bf16x3) ----
        float sc[8][4];
#pragma unroll
        for (int nt = 0; nt < 8; nt++)
#pragma unroll
            for (int i = 0; i < 4; i++) sc[nt][i] = 0.f;

#pragma unroll
        for (int ks = 0; ks < 4; ks++) {
            unsigned ah[4], al[4];
            const int rb = wid * 16;
            ah[0] = QH[(rb + g) * QSW + 8 * ks + t];
            ah[1] = QH[(rb + g + 8) * QSW + 8 * ks + t];
            ah[2] = QH[(rb + g) * QSW + 8 * ks + t + 4];
            ah[3] = QH[(rb + g + 8) * QSW + 8 * ks + t + 4];
            al[0] = QL[(rb + g) * QSW + 8 * ks + t];
            al[1] = QL[(rb + g + 8) * QSW + 8 * ks + t];
            al[2] = QL[(rb + g) * QSW + 8 * ks + t + 4];
            al[3] = QL[(rb + g + 8) * QSW + 8 * ks + t + 4];
#pragma unroll
            for (int nt = 0; nt < 8; nt++) {
                const int n = nt * 8 + g;
                unsigned bh[2], bl[2];
                bh[0] = KH[n * KSW + 8 * ks + t];
                bh[1] = KH[n * KSW + 8 * ks + t + 4];
                bl[0] = KL[n * KSW + 8 * ks + t];
                bl[1] = KL[n * KSW + 8 * ks + t + 4];
                mma16(sc[nt], ah, bh);
                mma16(sc[nt], al, bh);
                mma16(sc[nt], ah, bl);
            }
        }

        // ---- scale + causal mask ----
        const bool needmask = (j * 64 + 63) > rowbase;
#pragma unroll
        for (int nt = 0; nt < 8; nt++) {
#pragma unroll
            for (int cc = 0; cc < 4; cc++) {
                float v = sc[nt][cc] * 0.125f;
                if (needmask) {
                    int col = j * 64 + nt * 8 + 2 * t + (cc & 1);
                    int row = rowbase + g + ((cc >> 1) << 3);
                    if (col > row) v = -1e30f;
                }
                sc[nt][cc] = v;
            }
        }

        // ---- online softmax + entropy ----
        float mt0 = -1e30f, mt1 = -1e30f;
#pragma unroll
        for (int nt = 0; nt < 8; nt++) {
            mt0 = fmaxf(mt0, fmaxf(sc[nt][0], sc[nt][1]));
            mt1 = fmaxf(mt1, fmaxf(sc[nt][2], sc[nt][3]));
        }
        mt0 = fmaxf(mt0, __shfl_xor_sync(0xffffffffu, mt0, 1));
        mt0 = fmaxf(mt0, __shfl_xor_sync(0xffffffffu, mt0, 2));
        mt1 = fmaxf(mt1, __shfl_xor_sync(0xffffffffu, mt1, 1));
        mt1 = fmaxf(mt1, __shfl_xor_sync(0xffffffffu, mt1, 2));

        const float mn0 = fmaxf(m0, mt0), mn1 = fmaxf(m1, mt1);
        const float ex0 = __expf(m0 - mn0), ex1 = __expf(m1 - mn1);

        float ls0 = 0.f, ls1 = 0.f, as0 = 0.f, as1 = 0.f;
#pragma unroll
        for (int nt = 0; nt < 8; nt++) {
            float s0 = sc[nt][0], s1 = sc[nt][1];
            float s2 = sc[nt][2], s3 = sc[nt][3];
            float p0 = __expf(s0 - mn0), p1 = __expf(s1 - mn0);
            float p2 = __expf(s2 - mn1), p3 = __expf(s3 - mn1);
            sc[nt][0] = p0; sc[nt][1] = p1; sc[nt][2] = p2; sc[nt][3] = p3;
            ls0 += p0 + p1;           ls1 += p2 + p3;
            as0 += p0 * s0 + p1 * s1; as1 += p2 * s2 + p3 * s3;
        }
        ls0 += __shfl_xor_sync(0xffffffffu, ls0, 1);
        ls0 += __shfl_xor_sync(0xffffffffu, ls0, 2);
        ls1 += __shfl_xor_sync(0xffffffffu, ls1, 1);
        ls1 += __shfl_xor_sync(0xffffffffu, ls1, 2);
        as0 += __shfl_xor_sync(0xffffffffu, as0, 1);
        as0 += __shfl_xor_sync(0xffffffffu, as0, 2);
        as1 += __shfl_xor_sync(0xffffffffu, as1, 1);
        as1 += __shfl_xor_sync(0xffffffffu, as1, 2);

        l0s = l0s * ex0 + ls0;  aa0 = aa0 * ex0 + as0;  m0 = mn0;
        l1s = l1s * ex1 + ls1;  aa1 = aa1 * ex1 + as1;  m1 = mn1;

        // rescale O
#pragma unroll
        for (int nt = 0; nt < 8; nt++) {
            oc[nt][0] *= ex0; oc[nt][1] *= ex0;
            oc[nt][2] *= ex1; oc[nt][3] *= ex1;
        }

        // ---- pack P (C-layout pairs ARE the k16 A-fragments) ----
        unsigned ph0[8], pl0[8], ph1[8], pl1[8];
#pragma unroll
        for (int nt = 0; nt < 8; nt++) {
            split2(sc[nt][0], sc[nt][1], ph0[nt], pl0[nt]);
            split2(sc[nt][2], sc[nt][3], ph1[nt], pl1[nt]);
        }

        // ---- O += P @ V ----
#pragma unroll
        for (int ks = 0; ks < 4; ks++) {
            unsigned aH[4] = {ph0[2 * ks], ph1[2 * ks], ph0[2 * ks + 1], ph1[2 * ks + 1]};
            unsigned aL[4] = {pl0[2 * ks], pl1[2 * ks], pl0[2 * ks + 1], pl1[2 * ks + 1]};
#pragma unroll
            for (int nt = 0; nt < 8; nt++) {
                const int n = nt * 8 + g;
                unsigned bh[2], bl[2];
                bh[0] = VH[n * VSW + 8 * ks + t];
                bh[1] = VH[n * VSW + 8 * ks + t + 4];
                bl[0] = VL[n * VSW + 8 * ks + t];
                bl[1] = VL[n * VSW + 8 * ks + t + 4];
                mma16(oc[nt], aH, bh);
                mma16(oc[nt], aL, bh);
                mma16(oc[nt], aH, bl);
            }
        }
    }

    // ---- write O / l ----
    const float inv0 = 1.f / l0s, inv1 = 1.f / l1s;
    const int row0 = rowbase + g;
#pragma unroll
    for (int nt = 0; nt < 8; nt++) {
        const int col = h * DHEAD + nt * 8 + 2 * t;
        size_t gi = ((size_t)b * TQ + row0) * CDIM + col;
        float2 v0 = make_float2(oc[nt][0] * inv0, oc[nt][1] * inv0);
        float2 v1 = make_float2(oc[nt][2] * inv1, oc[nt][3] * inv1);
        *(float2*)&g_yatt[gi]            = v0;
        *(float2*)&g_yatt[gi + 8 * CDIM] = v1;
    }

    // ---- entropy partial ----
    if (t == 0) {
        float H = (m0 + __logf(l0s) - aa0 / l0s) + (m1 + __logf(l1s) - aa1 / l1s);
        sred[wid * 8 + g] = H;
    }
    __syncthreads();
    if (tid == 0) {
        float s = 0.f;
#pragma unroll 8
        for (int r = 0; r < 64; r++) s += sred[r];
        g_ent[((size_t)b * NHEAD + h) * NQT2 + qt] = s;
    }
}

// =====================================================================
// Final entropy reduction -> d_out[out_size-1]
// =====================================================================
__global__ void ent_final_kernel(float* __restrict__ out, int out_size)
{
    __shared__ float red[256];
    int tid = threadIdx.x;
    float s = 0.f;
    for (int i = tid; i < BATCH * NHEAD * NQT2; i += 256) s += g_ent[i];
    red[tid] = s;
    __syncthreads();
    for (int st = 128; st > 0; st >>= 1) {
        if (tid < st) red[tid] += red[tid + st];
        __syncthreads();
    }
    if (tid == 0) out[out_size - 1] = red[0] / (float)NROWS;
}

// =====================================================================
// launch
// =====================================================================
extern "C" void kernel_launch(void* const* d_in, const int* in_sizes, int n_in,
                              void* d_out, int out_size)
{
    const float* x      = (const float*)d_in[0];
    const float* w_attn = (const float*)d_in[1];
    const float* w_proj = (const float*)d_in[2];
    float* out = (float*)d_out;
    (void)in_sizes; (void)n_in;

    float *qkv_ptr, *yatt_ptr;
    cudaGetSymbolAddress((void**)&qkv_ptr,  g_qkv);
    cudaGetSymbolAddress((void**)&yatt_ptr, g_yatt);

    const int GEMM_SMEM  = 2 * GSTG * 4;        // 69,632 B
    const int FLASH_SMEM = FLASH_WORDS * 4;     // 72,448 B
    cudaFuncSetAttribute(gemm_bf3,
                         cudaFuncAttributeMaxDynamicSharedMemorySize, GEMM_SMEM);
    cudaFuncSetAttribute(flash_bf3,
                         cudaFuncAttributeMaxDynamicSharedMemorySize, FLASH_SMEM);

    // 1) qkv = x @ w_attn
    {
        dim3 grid(C3 / 128, (BATCH * TQ) / 128);
        gemm_bf3<<<grid, 256, GEMM_SMEM>>>(x, w_attn, qkv_ptr, BATCH * TQ, C3, CDIM);
    }
    // 2) flash attention + entropy partials
    {
        dim3 grid(NQT2, NHEAD, BATCH);
        flash_bf3<<<grid, 256, FLASH_SMEM>>>();
    }
    // 3) y = yatt @ w_proj -> d_out
    {
        dim3 grid(CDIM / 128, (BATCH * TQ) / 128);
        gemm_bf3<<<grid, 256, GEMM_SMEM>>>(yatt_ptr, w_proj, out, BATCH * TQ, CDIM, CDIM);
    }
    // 4) entropy scalar
    ent_final_kernel<<<1, 256>>>(out, out_size);
}

// round 5
// speedup vs baseline: 2.5740x; 1.3057x over previous
#include <cuda_runtime.h>
#include <cuda_bf16.h>
#include <stdint.h>

// ---------------- problem constants ----------------
#define BATCH  2
#define TQ     2048
#define CDIM   1024
#define NHEAD  16
#define DHEAD  64
#define C3     (3 * CDIM)
#define NQT2   (TQ / 128)
#define NROWS  (BATCH * NHEAD * TQ)
#define QKVN   (BATCH * NHEAD * TQ * DHEAD)

// ---------------- pre-split bf16 hi/lo planes (device scratch) ----------------
__device__ __align__(16) __nv_bfloat16 gXh[BATCH*TQ*CDIM],  gXl[BATCH*TQ*CDIM];
__device__ __align__(16) __nv_bfloat16 gWAh[CDIM*C3],       gWAl[CDIM*C3];
__device__ __align__(16) __nv_bfloat16 gWPh[CDIM*CDIM],     gWPl[CDIM*CDIM];
__device__ __align__(16) __nv_bfloat16 gQh[QKVN], gQl[QKVN];
__device__ __align__(16) __nv_bfloat16 gKh[QKVN], gKl[QKVN];
__device__ __align__(16) __nv_bfloat16 gVh[QKVN], gVl[QKVN];
__device__ __align__(16) __nv_bfloat16 gYh[BATCH*TQ*CDIM],  gYl[BATCH*TQ*CDIM];
__device__ float g_ent[BATCH * NHEAD * NQT2];

// ---------------- helpers ----------------
__device__ __forceinline__ void split2(float a, float b, unsigned& hi, unsigned& lo) {
    __nv_bfloat162 h = __floats2bfloat162_rn(a, b);
    float ra = a - __bfloat162float(h.x);
    float rb = b - __bfloat162float(h.y);
    __nv_bfloat162 l = __floats2bfloat162_rn(ra, rb);
    hi = *reinterpret_cast<unsigned*>(&h);
    lo = *reinterpret_cast<unsigned*>(&l);
}
__device__ __forceinline__ void mma16(float* c, const unsigned* a, unsigned b0, unsigned b1) {
    asm volatile(
        "mma.sync.aligned.m16n8k16.row.col.f32.bf16.bf16.f32 "
        "{%0,%1,%2,%3},{%4,%5,%6,%7},{%8,%9},{%0,%1,%2,%3};"
        : "+f"(c[0]), "+f"(c[1]), "+f"(c[2]), "+f"(c[3])
        : "r"(a[0]), "r"(a[1]), "r"(a[2]), "r"(a[3]), "r"(b0), "r"(b1));
}
__device__ __forceinline__ void ldsm4(unsigned& r0, unsigned& r1, unsigned& r2, unsigned& r3, uint32_t a) {
    asm volatile("ldmatrix.sync.aligned.m8n8.x4.shared.b16 {%0,%1,%2,%3},[%4];"
        : "=r"(r0), "=r"(r1), "=r"(r2), "=r"(r3) : "r"(a));
}
__device__ __forceinline__ void ldsm4t(unsigned& r0, unsigned& r1, unsigned& r2, unsigned& r3, uint32_t a) {
    asm volatile("ldmatrix.sync.aligned.m8n8.x4.trans.shared.b16 {%0,%1,%2,%3},[%4];"
        : "=r"(r0), "=r"(r1), "=r"(r2), "=r"(r3) : "r"(a));
}
__device__ __forceinline__ void cpa16(uint32_t d, const void* s) {
    asm volatile("cp.async.ca.shared.global [%0],[%1],16;" :: "r"(d), "l"(s));
}
#define CP_COMMIT() asm volatile("cp.async.commit_group;" ::: "memory")
#define CP_WAIT(N)  asm volatile("cp.async.wait_group %0;" :: "n"(N) : "memory")

// =====================================================================
// prep: elementwise fp32 -> bf16 hi/lo planes
// =====================================================================
__global__ void split_kernel(const float* __restrict__ in,
                             __nv_bfloat16* __restrict__ hi,
                             __nv_bfloat16* __restrict__ lo, int n4)
{
    int i = blockIdx.x * blockDim.x + threadIdx.x;
    if (i < n4) {
        float4 v = ((const float4*)in)[i];
        unsigned h0, l0, h1, l1;
        split2(v.x, v.y, h0, l0); split2(v.z, v.w, h1, l1);
        ((uint2*)hi)[i] = make_uint2(h0, h1);
        ((uint2*)lo)[i] = make_uint2(l0, l1);
    }
}

// =====================================================================
// GEMM (pre-split bf16x3): C = A @ B. A [M][K], B [K][N] bf16 hi/lo planes.
// Block 128x128, BK=32, 256 threads, 3-stage cp.async, ldmatrix frags.
// mode 0: fp32 C; mode 1: scatter into qkv planes.
// =====================================================================
#define GSTG 32768
extern __shared__ char dsm[];

__device__ __forceinline__ void gemm_issue(
    uint32_t s0, const __nv_bfloat16* Ah, const __nv_bfloat16* Al,
    const __nv_bfloat16* Bh, const __nv_bfloat16* Bl,
    int bm, int bn, int k0, int K, int N, int tid)
{
#pragma unroll
    for (int it = 0; it < 2; it++) {
        int id = tid + it * 256;
        int r = id >> 2, c = id & 3;
        uint32_t d = s0 + r * 64 + ((c ^ ((r >> 1) & 3)) << 4);
        size_t go = (size_t)(bm + r) * K + k0 + c * 8;
        cpa16(d,        Ah + go);
        cpa16(d + 8192, Al + go);
    }
#pragma unroll
    for (int it = 0; it < 2; it++) {
        int id = tid + it * 256;
        int k = id >> 4, c = id & 15;
        uint32_t d = s0 + 16384 + k * 256 + ((c ^ (k & 7)) << 4);
        size_t go = (size_t)(k0 + k) * N + bn + c * 8;
        cpa16(d,        Bh + go);
        cpa16(d + 8192, Bl + go);
    }
}

__global__ __launch_bounds__(256) void gemm_pre(
    const __nv_bfloat16* __restrict__ Ah, const __nv_bfloat16* __restrict__ Al,
    const __nv_bfloat16* __restrict__ Bh, const __nv_bfloat16* __restrict__ Bl,
    float* __restrict__ C, int M, int N, int K, int mode)
{
    const uint32_t sb = (uint32_t)__cvta_generic_to_shared(dsm);
    const int tid = threadIdx.x, lane = tid & 31, wid = tid >> 5;
    const int g = lane >> 2, t = lane & 3;
    const int m8 = lane >> 3, ri = lane & 7;
    const int wm = wid & 3, wn = wid >> 2;
    const int bm = blockIdx.y * 128, bn = blockIdx.x * 128;

    float acc[2][8][4];
#pragma unroll
    for (int mt = 0; mt < 2; mt++)
#pragma unroll
        for (int nt = 0; nt < 8; nt++)
#pragma unroll
            for (int i = 0; i < 4; i++) acc[mt][nt][i] = 0.f;

    const int NCH = K / 32;
    gemm_issue(sb,        Ah, Al, Bh, Bl, bm, bn, 0,  K, N, tid); CP_COMMIT();
    gemm_issue(sb + GSTG, Ah, Al, Bh, Bl, bm, bn, 32, K, N, tid); CP_COMMIT();

    for (int ch = 0; ch < NCH; ch++) {
        if (ch + 2 < NCH)
            gemm_issue(sb + ((ch + 2) % 3) * GSTG, Ah, Al, Bh, Bl,
                       bm, bn, (ch + 2) * 32, K, N, tid);
        CP_COMMIT();
        CP_WAIT(2);
        __syncthreads();

        const uint32_t s0 = sb + (ch % 3) * GSTG;
#pragma unroll
        for (int ks = 0; ks < 2; ks++) {
            unsigned ah[2][4], al[2][4];
#pragma unroll
            for (int mt = 0; mt < 2; mt++) {
                int row = wm * 32 + mt * 16 + (m8 & 1) * 8 + ri;
                int c4  = 2 * ks + (m8 >> 1);
                uint32_t a = s0 + row * 64 + ((c4 ^ ((row >> 1) & 3)) << 4);
                ldsm4(ah[mt][0], ah[mt][1], ah[mt][2], ah[mt][3], a);
                ldsm4(al[mt][0], al[mt][1], al[mt][2], al[mt][3], a + 8192);
            }
#pragma unroll
            for (int ntp = 0; ntp < 4; ntp++) {
                int kr = 16 * ks + (m8 & 1) * 8 + ri;
                int cc = wn * 8 + ntp * 2 + (m8 >> 1);
                uint32_t ba = s0 + 16384 + kr * 256 + ((cc ^ (kr & 7)) << 4);
                unsigned bh[4], bl[4];
                ldsm4t(bh[0], bh[1], bh[2], bh[3], ba);
                ldsm4t(bl[0], bl[1], bl[2], bl[3], ba + 8192);
#pragma unroll
                for (int hf = 0; hf < 2; hf++) {
                    unsigned b0h = bh[2*hf], b1h = bh[2*hf+1];
                    unsigned b0l = bl[2*hf], b1l = bl[2*hf+1];
#pragma unroll
                    for (int mt = 0; mt < 2; mt++) {
                        float* cr = acc[mt][ntp * 2 + hf];
                        mma16(cr, ah[mt], b0h, b1h);
                        mma16(cr, al[mt], b0h, b1h);
                        mma16(cr, ah[mt], b0l, b1l);
                    }
                }
            }
        }
        __syncthreads();
    }

    // ---- epilogue ----
    if (mode == 0) {
#pragma unroll
        for (int mt = 0; mt < 2; mt++) {
#pragma unroll
            for (int nt = 0; nt < 8; nt++) {
                const int row = bm + wm * 32 + mt * 16 + g;
                const int col = bn + wn * 64 + nt * 8 + 2 * t;
                *(float2*)&C[(size_t)row * N + col] =
                    make_float2(acc[mt][nt][0], acc[mt][nt][1]);
                *(float2*)&C[(size_t)(row + 8) * N + col] =
                    make_float2(acc[mt][nt][2], acc[mt][nt][3]);
            }
        }
    } else {
#pragma unroll
        for (int mt = 0; mt < 2; mt++) {
#pragma unroll
            for (int nt = 0; nt < 8; nt++) {
                const int row = bm + wm * 32 + mt * 16 + g;
                const int col = bn + wn * 64 + nt * 8 + 2 * t;
                const int sec = col >> 10, hh = (col >> 6) & 15, d = col & 63;
                const int bb = row >> 11, tok = row & 2047;
                size_t idx = (((size_t)bb * NHEAD + hh) * TQ + tok) * DHEAD + d;
                __nv_bfloat16* hp = sec == 0 ? gQh : (sec == 1 ? gKh : gVh);
                __nv_bfloat16* lp = sec == 0 ? gQl : (sec == 1 ? gKl : gVl);
                unsigned hw, lw;
                split2(acc[mt][nt][0], acc[mt][nt][1], hw, lw);
                *(unsigned*)&hp[idx] = hw; *(unsigned*)&lp[idx] = lw;
                split2(acc[mt][nt][2], acc[mt][nt][3], hw, lw);
                *(unsigned*)&hp[idx + 8 * DHEAD] = hw;
                *(unsigned*)&lp[idx + 8 * DHEAD] = lw;
            }
        }
    }
}

// =====================================================================
// Flash attention: pre-split planes + cp.async KV double-buffer + ldmatrix.
// Grid (NQT2, NHEAD, BATCH), 256 thr, warp: 16 rows x 64 keys.
// =====================================================================
#define FKV0 32768
#define FSTG 32768

__device__ __forceinline__ void flash_issue_kv(uint32_t s0, size_t base, int j, int tid)
{
#pragma unroll
    for (int it = 0; it < 2; it++) {
        int id = tid + it * 256;
        int r = id >> 3, c = id & 7;
        uint32_t d = s0 + r * 128 + ((c ^ (r & 7)) << 4);
        size_t go = base + (size_t)(j * 64 + r) * DHEAD + c * 8;
        cpa16(d,         gKh + go);
        cpa16(d + 8192,  gKl + go);
        cpa16(d + 16384, gVh + go);
        cpa16(d + 24576, gVl + go);
    }
}

__global__ __launch_bounds__(256) void flash_pre()
{
    __shared__ float sred[64];
    const uint32_t sb = (uint32_t)__cvta_generic_to_shared(dsm);
    const int qt = blockIdx.x, h = blockIdx.y, b = blockIdx.z;
    const int tid = threadIdx.x, lane = tid & 31, wid = tid >> 5;
    const int g = lane >> 2, t = lane & 3;
    const int m8 = lane >> 3, ri = lane & 7;
    const size_t base = (size_t)(b * NHEAD + h) * TQ * DHEAD;

    // ---- Q hi/lo cp.async ----
#pragma unroll
    for (int it = 0; it < 4; it++) {
        int id = tid + it * 256;
        int r = id >> 3, c = id & 7;
        uint32_t d = sb + r * 128 + ((c ^ (r & 7)) << 4);
        size_t go = base + (size_t)(qt * 128 + r) * DHEAD + c * 8;
        cpa16(d,         gQh + go);
        cpa16(d + 16384, gQl + go);
    }
    CP_COMMIT();
    flash_issue_kv(sb + FKV0, base, 0, tid); CP_COMMIT();
    CP_WAIT(1);
    __syncthreads();

    // ---- hoist Q fragments (constant across j) ----
    unsigned qh[4][4], ql[4][4];
#pragma unroll
    for (int ks = 0; ks < 4; ks++) {
        int row = wid * 16 + (m8 & 1) * 8 + ri;
        int c = 2 * ks + (m8 >> 1);
        uint32_t a = sb + row * 128 + ((c ^ (row & 7)) << 4);
        ldsm4(qh[ks][0], qh[ks][1], qh[ks][2], qh[ks][3], a);
        ldsm4(ql[ks][0], ql[ks][1], ql[ks][2], ql[ks][3], a + 16384);
    }

    float oc[8][4];
#pragma unroll
    for (int nt = 0; nt < 8; nt++)
#pragma unroll
        for (int i = 0; i < 4; i++) oc[nt][i] = 0.f;

    float m0 = -1e30f, m1 = -1e30f, l0s = 0.f, l1s = 0.f, aa0 = 0.f, aa1 = 0.f;
    const int rowbase = qt * 128 + wid * 16;
    const int nj = 2 * qt + 2;

    for (int j = 0; j < nj; j++) {
        if (j + 1 < nj) flash_issue_kv(sb + FKV0 + ((j + 1) & 1) * FSTG, base, j + 1, tid);
        CP_COMMIT();
        CP_WAIT(1);
        __syncthreads();
        const uint32_t kv = sb + FKV0 + (j & 1) * FSTG;

        // ---- S = Q K^T ----
        float sc[8][4];
#pragma unroll
        for (int nt = 0; nt < 8; nt++)
#pragma unroll
            for (int i = 0; i < 4; i++) sc[nt][i] = 0.f;

#pragma unroll
        for (int ks = 0; ks < 4; ks++) {
#pragma unroll
            for (int ntp = 0; ntp < 4; ntp++) {
                int kr = ntp * 16 + (m8 & 1) * 8 + ri;
                int c = 2 * ks + (m8 >> 1);
                uint32_t ka = kv + kr * 128 + ((c ^ (kr & 7)) << 4);
                unsigned kh[4], kl[4];
                ldsm4(kh[0], kh[1], kh[2], kh[3], ka);
                ldsm4(kl[0], kl[1], kl[2], kl[3], ka + 8192);
                // b(nt)={kh[0],kh[2]}, b(nt+1)={kh[1],kh[3]}
                mma16(sc[2*ntp],   qh[ks], kh[0], kh[2]);
                mma16(sc[2*ntp],   ql[ks], kh[0], kh[2]);
                mma16(sc[2*ntp],   qh[ks], kl[0], kl[2]);
                mma16(sc[2*ntp+1], qh[ks], kh[1], kh[3]);
                mma16(sc[2*ntp+1], ql[ks], kh[1], kh[3]);
                mma16(sc[2*ntp+1], qh[ks], kl[1], kl[3]);
            }
        }

        // ---- scale + causal mask ----
        const bool needmask = (j * 64 + 63) > rowbase;
#pragma unroll
        for (int nt = 0; nt < 8; nt++) {
#pragma unroll
            for (int cc = 0; cc < 4; cc++) {
                float v = sc[nt][cc] * 0.125f;
                if (needmask) {
                    int col = j * 64 + nt * 8 + 2 * t + (cc & 1);
                    int row = rowbase + g + ((cc >> 1) << 3);
                    if (col > row) v = -1e30f;
                }
                sc[nt][cc] = v;
            }
        }

        // ---- online softmax + entropy ----
        float mt0 = -1e30f, mt1 = -1e30f;
#pragma unroll
        for (int nt = 0; nt < 8; nt++) {
            mt0 = fmaxf(mt0, fmaxf(sc[nt][0], sc[nt][1]));
            mt1 = fmaxf(mt1, fmaxf(sc[nt][2], sc[nt][3]));
        }
        mt0 = fmaxf(mt0, __shfl_xor_sync(0xffffffffu, mt0, 1));
        mt0 = fmaxf(mt0, __shfl_xor_sync(0xffffffffu, mt0, 2));
        mt1 = fmaxf(mt1, __shfl_xor_sync(0xffffffffu, mt1, 1));
        mt1 = fmaxf(mt1, __shfl_xor_sync(0xffffffffu, mt1, 2));

        const float mn0 = fmaxf(m0, mt0), mn1 = fmaxf(m1, mt1);
        const float ex0 = __expf(m0 - mn0), ex1 = __expf(m1 - mn1);

        float ls0 = 0.f, ls1 = 0.f, as0 = 0.f, as1 = 0.f;
#pragma unroll
        for (int nt = 0; nt < 8; nt++) {
            float s0 = sc[nt][0], s1 = sc[nt][1];
            float s2 = sc[nt][2], s3 = sc[nt][3];
            float p0 = __expf(s0 - mn0), p1 = __expf(s1 - mn0);
            float p2 = __expf(s2 - mn1), p3 = __expf(s3 - mn1);
            sc[nt][0] = p0; sc[nt][1] = p1; sc[nt][2] = p2; sc[nt][3] = p3;
            ls0 += p0 + p1;           ls1 += p2 + p3;
            as0 += p0 * s0 + p1 * s1; as1 += p2 * s2 + p3 * s3;
        }
        ls0 += __shfl_xor_sync(0xffffffffu, ls0, 1);
        ls0 += __shfl_xor_sync(0xffffffffu, ls0, 2);
        ls1 += __shfl_xor_sync(0xffffffffu, ls1, 1);
        ls1 += __shfl_xor_sync(0xffffffffu, ls1, 2);
        as0 += __shfl_xor_sync(0xffffffffu, as0, 1);
        as0 += __shfl_xor_sync(0xffffffffu, as0, 2);
        as1 += __shfl_xor_sync(0xffffffffu, as1, 1);
        as1 += __shfl_xor_sync(0xffffffffu, as1, 2);

        l0s = l0s * ex0 + ls0;  aa0 = aa0 * ex0 + as0;  m0 = mn0;
        l1s = l1s * ex1 + ls1;  aa1 = aa1 * ex1 + as1;  m1 = mn1;

#pragma unroll
        for (int nt = 0; nt < 8; nt++) {
            oc[nt][0] *= ex0; oc[nt][1] *= ex0;
            oc[nt][2] *= ex1; oc[nt][3] *= ex1;
        }

        // ---- pack P (C-frag pairs == k16 A-frags) ----
        unsigned ph0[8], pl0[8], ph1[8], pl1[8];
#pragma unroll
        for (int nt = 0; nt < 8; nt++) {
            split2(sc[nt][0], sc[nt][1], ph0[nt], pl0[nt]);
            split2(sc[nt][2], sc[nt][3], ph1[nt], pl1[nt]);
        }

        // ---- O += P @ V (V b-frags via ldmatrix.trans on natural layout) ----
#pragma unroll
        for (int ks = 0; ks < 4; ks++) {
            unsigned aH[4] = {ph0[2*ks], ph1[2*ks], ph0[2*ks+1], ph1[2*ks+1]};
            unsigned aL[4] = {pl0[2*ks], pl1[2*ks], pl0[2*ks+1], pl1[2*ks+1]};
#pragma unroll
            for (int ntp = 0; ntp < 4; ntp++) {
                int vr = 16 * ks + (m8 & 1) * 8 + ri;
                int c = ntp * 2 + (m8 >> 1);
                uint32_t va = kv + 16384 + vr * 128 + ((c ^ (vr & 7)) << 4);
                unsigned vh[4], vl[4];
                ldsm4t(vh[0], vh[1], vh[2], vh[3], va);
                ldsm4t(vl[0], vl[1], vl[2], vl[3], va + 8192);
                mma16(oc[2*ntp],   aH, vh[0], vh[1]);
                mma16(oc[2*ntp],   aL, vh[0], vh[1]);
                mma16(oc[2*ntp],   aH, vl[0], vl[1]);
                mma16(oc[2*ntp+1], aH, vh[2], vh[3]);
                mma16(oc[2*ntp+1], aL, vh[2], vh[3]);
                mma16(oc[2*ntp+1], aH, vl[2], vl[3]);
            }
        }
        __syncthreads();
    }

    // ---- epilogue: write yatt hi/lo planes ----
    const float inv0 = 1.f / l0s, inv1 = 1.f / l1s;
    const int trow = rowbase + g;
#pragma unroll
    for (int nt = 0; nt < 8; nt++) {
        const int col = h * DHEAD + nt * 8 + 2 * t;
        size_t idx = ((size_t)b * TQ + trow) * CDIM + col;
        unsigned hw, lw;
        split2(oc[nt][0] * inv0, oc[nt][1] * inv0, hw, lw);
        *(unsigned*)&gYh[idx] = hw; *(unsigned*)&gYl[idx] = lw;
        split2(oc[nt][2] * inv1, oc[nt][3] * inv1, hw, lw);
        *(unsigned*)&gYh[idx + 8 * CDIM] = hw; *(unsigned*)&gYl[idx + 8 * CDIM] = lw;
    }

    // ---- entropy partial ----
    if (t == 0) {
        float H = (m0 + __logf(l0s) - aa0 / l0s) + (m1 + __logf(l1s) - aa1 / l1s);
        sred[wid * 8 + g] = H;
    }
    __syncthreads();
    if (tid == 0) {
        float s = 0.f;
#pragma unroll 8
        for (int r = 0; r < 64; r++) s += sred[r];
        g_ent[((size_t)b * NHEAD + h) * NQT2 + qt] = s;
    }
}

// =====================================================================
// entropy final reduction
// =====================================================================
__global__ void ent_final_kernel(float* __restrict__ out, int out_size)
{
    __shared__ float red[256];
    int tid = threadIdx.x;
    float s = 0.f;
    for (int i = tid; i < BATCH * NHEAD * NQT2; i += 256) s += g_ent[i];
    red[tid] = s;
    __syncthreads();
    for (int st = 128; st > 0; st >>= 1) {
        if (tid < st) red[tid] += red[tid + st];
        __syncthreads();
    }
    if (tid == 0) out[out_size - 1] = red[0] / (float)NROWS;
}

// =====================================================================
// launch
// =====================================================================
extern "C" void kernel_launch(void* const* d_in, const int* in_sizes, int n_in,
                              void* d_out, int out_size)
{
    const float* x      = (const float*)d_in[0];
    const float* w_attn = (const float*)d_in[1];
    const float* w_proj = (const float*)d_in[2];
    float* out = (float*)d_out;
    (void)in_sizes; (void)n_in;

    __nv_bfloat16 *xh, *xl, *wah, *wal, *wph, *wpl, *yh, *yl;
    cudaGetSymbolAddress((void**)&xh,  gXh);  cudaGetSymbolAddress((void**)&xl,  gXl);
    cudaGetSymbolAddress((void**)&wah, gWAh); cudaGetSymbolAddress((void**)&wal, gWAl);
    cudaGetSymbolAddress((void**)&wph, gWPh); cudaGetSymbolAddress((void**)&wpl, gWPl);
    cudaGetSymbolAddress((void**)&yh,  gYh);  cudaGetSymbolAddress((void**)&yl,  gYl);

    const int GEMM_SMEM  = 3 * GSTG;   // 98304
    const int FLASH_SMEM = 98304;
    cudaFuncSetAttribute(gemm_pre,
                         cudaFuncAttributeMaxDynamicSharedMemorySize, GEMM_SMEM);
    cudaFuncSetAttribute(flash_pre,
                         cudaFuncAttributeMaxDynamicSharedMemorySize, FLASH_SMEM);

    // 0) split inputs
    {
        int n4x = BATCH * TQ * CDIM / 4;
        split_kernel<<<(n4x + 255) / 256, 256>>>(x, xh, xl, n4x);
        int n4a = CDIM * C3 / 4;
        split_kernel<<<(n4a + 255) / 256, 256>>>(w_attn, wah, wal, n4a);
        int n4p = CDIM * CDIM / 4;
        split_kernel<<<(n4p + 255) / 256, 256>>>(w_proj, wph, wpl, n4p);
    }
    // 1) qkv = x @ w_attn  -> split qkv planes (mode 1)
    {
        dim3 grid(C3 / 128, (BATCH * TQ) / 128);
        gemm_pre<<<grid, 256, GEMM_SMEM>>>(xh, xl, wah, wal, nullptr,
                                           BATCH * TQ, C3, CDIM, 1);
    }
    // 2) flash attention + entropy partials -> gY planes
    {
        dim3 grid(NQT2, NHEAD, BATCH);
        flash_pre<<<grid, 256, FLASH_SMEM>>>();
    }
    // 3) y = yatt @ w_proj -> d_out (mode 0)
    {
        dim3 grid(CDIM / 128, (BATCH * TQ) / 128);
        gemm_pre<<<grid, 256, GEMM_SMEM>>>(yh, yl, wph, wpl, out,
                                           BATCH * TQ, CDIM, CDIM, 0);
    }
    // 4) entropy scalar
    ent_final_kernel<<<1, 256>>>(out, out_size);
}

// round 6
// speedup vs baseline: 2.6083x; 1.0133x over previous
#include <cuda_runtime.h>
#include <cuda_bf16.h>
#include <stdint.h>

// ---------------- problem constants ----------------
#define BATCH  2
#define TQ     2048
#define CDIM   1024
#define NHEAD  16
#define DHEAD  64
#define C3     (3 * CDIM)
#define NQT2   (TQ / 128)
#define NROWS  (BATCH * NHEAD * TQ)
#define QKVN   (BATCH * NHEAD * TQ * DHEAD)

// ---------------- pre-split bf16 hi/lo planes (device scratch) ----------------
__device__ __align__(16) __nv_bfloat16 gXh[BATCH*TQ*CDIM],  gXl[BATCH*TQ*CDIM];
__device__ __align__(16) __nv_bfloat16 gWAh[CDIM*C3],       gWAl[CDIM*C3];
__device__ __align__(16) __nv_bfloat16 gWPh[CDIM*CDIM],     gWPl[CDIM*CDIM];
__device__ __align__(16) __nv_bfloat16 gQh[QKVN], gQl[QKVN];
__device__ __align__(16) __nv_bfloat16 gKh[QKVN], gKl[QKVN];
__device__ __align__(16) __nv_bfloat16 gVh[QKVN], gVl[QKVN];
__device__ __align__(16) __nv_bfloat16 gYh[BATCH*TQ*CDIM],  gYl[BATCH*TQ*CDIM];
__device__ float g_ent[BATCH * NHEAD * NQT2];

// ---------------- helpers ----------------
__device__ __forceinline__ void split2(float a, float b, unsigned& hi, unsigned& lo) {
    __nv_bfloat162 h = __floats2bfloat162_rn(a, b);
    float ra = a - __bfloat162float(h.x);
    float rb = b - __bfloat162float(h.y);
    __nv_bfloat162 l = __floats2bfloat162_rn(ra, rb);
    hi = *reinterpret_cast<unsigned*>(&h);
    lo = *reinterpret_cast<unsigned*>(&l);
}
__device__ __forceinline__ void mma16(float* c, const unsigned* a, unsigned b0, unsigned b1) {
    asm volatile(
        "mma.sync.aligned.m16n8k16.row.col.f32.bf16.bf16.f32 "
        "{%0,%1,%2,%3},{%4,%5,%6,%7},{%8,%9},{%0,%1,%2,%3};"
        : "+f"(c[0]), "+f"(c[1]), "+f"(c[2]), "+f"(c[3])
        : "r"(a[0]), "r"(a[1]), "r"(a[2]), "r"(a[3]), "r"(b0), "r"(b1));
}
__device__ __forceinline__ void ldsm4(unsigned& r0, unsigned& r1, unsigned& r2, unsigned& r3, uint32_t a) {
    asm volatile("ldmatrix.sync.aligned.m8n8.x4.shared.b16 {%0,%1,%2,%3},[%4];"
        : "=r"(r0), "=r"(r1), "=r"(r2), "=r"(r3) : "r"(a));
}
__device__ __forceinline__ void ldsm4t(unsigned& r0, unsigned& r1, unsigned& r2, unsigned& r3, uint32_t a) {
    asm volatile("ldmatrix.sync.aligned.m8n8.x4.trans.shared.b16 {%0,%1,%2,%3},[%4];"
        : "=r"(r0), "=r"(r1), "=r"(r2), "=r"(r3) : "r"(a));
}
__device__ __forceinline__ void cpa16(uint32_t d, const void* s) {
    asm volatile("cp.async.ca.shared.global [%0],[%1],16;" :: "r"(d), "l"(s));
}
#define CP_COMMIT() asm volatile("cp.async.commit_group;" ::: "memory")
#define CP_WAIT(N)  asm volatile("cp.async.wait_group %0;" :: "n"(N) : "memory")

// =====================================================================
// prep: elementwise fp32 -> bf16 hi/lo planes
// =====================================================================
__global__ void split_kernel(const float* __restrict__ in,
                             __nv_bfloat16* __restrict__ hi,
                             __nv_bfloat16* __restrict__ lo, int n4)
{
    int i = blockIdx.x * blockDim.x + threadIdx.x;
    if (i < n4) {
        float4 v = ((const float4*)in)[i];
        unsigned h0, l0, h1, l1;
        split2(v.x, v.y, h0, l0); split2(v.z, v.w, h1, l1);
        ((uint2*)hi)[i] = make_uint2(h0, h1);
        ((uint2*)lo)[i] = make_uint2(l0, l1);
    }
}

// =====================================================================
// GEMM (pre-split bf16x3): C = A @ B. 128x128 tile, BK=32, 256 thr,
// 3-stage cp.async, ldmatrix frags. occ=2 via launch_bounds.
// =====================================================================
#define GSTG 32768
extern __shared__ char dsm[];

__device__ __forceinline__ void gemm_issue(
    uint32_t s0, const __nv_bfloat16* Ah, const __nv_bfloat16* Al,
    const __nv_bfloat16* Bh, const __nv_bfloat16* Bl,
    int bm, int bn, int k0, int K, int N, int tid)
{
#pragma unroll
    for (int it = 0; it < 2; it++) {
        int id = tid + it * 256;
        int r = id >> 2, c = id & 3;
        uint32_t d = s0 + r * 64 + ((c ^ ((r >> 1) & 3)) << 4);
        size_t go = (size_t)(bm + r) * K + k0 + c * 8;
        cpa16(d,        Ah + go);
        cpa16(d + 8192, Al + go);
    }
#pragma unroll
    for (int it = 0; it < 2; it++) {
        int id = tid + it * 256;
        int k = id >> 4, c = id & 15;
        uint32_t d = s0 + 16384 + k * 256 + ((c ^ (k & 7)) << 4);
        size_t go = (size_t)(k0 + k) * N + bn + c * 8;
        cpa16(d,        Bh + go);
        cpa16(d + 8192, Bl + go);
    }
}

__global__ __launch_bounds__(256, 2) void gemm_pre(
    const __nv_bfloat16* __restrict__ Ah, const __nv_bfloat16* __restrict__ Al,
    const __nv_bfloat16* __restrict__ Bh, const __nv_bfloat16* __restrict__ Bl,
    float* __restrict__ C, int M, int N, int K, int mode)
{
    const uint32_t sb = (uint32_t)__cvta_generic_to_shared(dsm);
    const int tid = threadIdx.x, lane = tid & 31, wid = tid >> 5;
    const int g = lane >> 2, t = lane & 3;
    const int m8 = lane >> 3, ri = lane & 7;
    const int wm = wid & 3, wn = wid >> 2;
    const int bm = blockIdx.y * 128, bn = blockIdx.x * 128;

    float acc[2][8][4];
#pragma unroll
    for (int mt = 0; mt < 2; mt++)
#pragma unroll
        for (int nt = 0; nt < 8; nt++)
#pragma unroll
            for (int i = 0; i < 4; i++) acc[mt][nt][i] = 0.f;

    const int NCH = K / 32;
    gemm_issue(sb,        Ah, Al, Bh, Bl, bm, bn, 0,  K, N, tid); CP_COMMIT();
    gemm_issue(sb + GSTG, Ah, Al, Bh, Bl, bm, bn, 32, K, N, tid); CP_COMMIT();

    for (int ch = 0; ch < NCH; ch++) {
        if (ch + 2 < NCH)
            gemm_issue(sb + ((ch + 2) % 3) * GSTG, Ah, Al, Bh, Bl,
                       bm, bn, (ch + 2) * 32, K, N, tid);
        CP_COMMIT();
        CP_WAIT(2);
        __syncthreads();

        const uint32_t s0 = sb + (ch % 3) * GSTG;
#pragma unroll
        for (int ks = 0; ks < 2; ks++) {
            unsigned ah[2][4], al[2][4];
#pragma unroll
            for (int mt = 0; mt < 2; mt++) {
                int row = wm * 32 + mt * 16 + (m8 & 1) * 8 + ri;
                int c4  = 2 * ks + (m8 >> 1);
                uint32_t a = s0 + row * 64 + ((c4 ^ ((row >> 1) & 3)) << 4);
                ldsm4(ah[mt][0], ah[mt][1], ah[mt][2], ah[mt][3], a);
                ldsm4(al[mt][0], al[mt][1], al[mt][2], al[mt][3], a + 8192);
            }
#pragma unroll
            for (int ntp = 0; ntp < 4; ntp++) {
                int kr = 16 * ks + (m8 & 1) * 8 + ri;
                int cc = wn * 8 + ntp * 2 + (m8 >> 1);
                uint32_t ba = s0 + 16384 + kr * 256 + ((cc ^ (kr & 7)) << 4);
                unsigned bh[4], bl[4];
                ldsm4t(bh[0], bh[1], bh[2], bh[3], ba);
                ldsm4t(bl[0], bl[1], bl[2], bl[3], ba + 8192);
#pragma unroll
                for (int hf = 0; hf < 2; hf++) {
                    unsigned b0h = bh[2*hf], b1h = bh[2*hf+1];
                    unsigned b0l = bl[2*hf], b1l = bl[2*hf+1];
#pragma unroll
                    for (int mt = 0; mt < 2; mt++) {
                        float* cr = acc[mt][ntp * 2 + hf];
                        mma16(cr, ah[mt], b0h, b1h);
                        mma16(cr, al[mt], b0h, b1h);
                        mma16(cr, ah[mt], b0l, b1l);
                    }
                }
            }
        }
        __syncthreads();
    }

    // ---- epilogue ----
    if (mode == 0) {
#pragma unroll
        for (int mt = 0; mt < 2; mt++) {
#pragma unroll
            for (int nt = 0; nt < 8; nt++) {
                const int row = bm + wm * 32 + mt * 16 + g;
                const int col = bn + wn * 64 + nt * 8 + 2 * t;
                *(float2*)&C[(size_t)row * N + col] =
                    make_float2(acc[mt][nt][0], acc[mt][nt][1]);
                *(float2*)&C[(size_t)(row + 8) * N + col] =
                    make_float2(acc[mt][nt][2], acc[mt][nt][3]);
            }
        }
    } else {
#pragma unroll
        for (int mt = 0; mt < 2; mt++) {
#pragma unroll
            for (int nt = 0; nt < 8; nt++) {
                const int row = bm + wm * 32 + mt * 16 + g;
                const int col = bn + wn * 64 + nt * 8 + 2 * t;
                const int sec = col >> 10, hh = (col >> 6) & 15, d = col & 63;
                const int bb = row >> 11, tok = row & 2047;
                size_t idx = (((size_t)bb * NHEAD + hh) * TQ + tok) * DHEAD + d;
                __nv_bfloat16* hp = sec == 0 ? gQh : (sec == 1 ? gKh : gVh);
                __nv_bfloat16* lp = sec == 0 ? gQl : (sec == 1 ? gKl : gVl);
                unsigned hw, lw;
                split2(acc[mt][nt][0], acc[mt][nt][1], hw, lw);
                *(unsigned*)&hp[idx] = hw; *(unsigned*)&lp[idx] = lw;
                split2(acc[mt][nt][2], acc[mt][nt][3], hw, lw);
                *(unsigned*)&hp[idx + 8 * DHEAD] = hw;
                *(unsigned*)&lp[idx + 8 * DHEAD] = lw;
            }
        }
    }
}

// =====================================================================
// Flash attention: 64KB smem (Q region reused as KV stage 1), occ=2.
// Grid (NQT2, NHEAD, BATCH), 256 thr, warp: 16 rows x 64 keys.
// =====================================================================
#define FSTG 32768

__device__ __forceinline__ void flash_issue_kv(uint32_t s0, size_t base, int j, int tid)
{
#pragma unroll
    for (int it = 0; it < 2; it++) {
        int id = tid + it * 256;
        int r = id >> 3, c = id & 7;
        uint32_t d = s0 + r * 128 + ((c ^ (r & 7)) << 4);
        size_t go = base + (size_t)(j * 64 + r) * DHEAD + c * 8;
        cpa16(d,         gKh + go);
        cpa16(d + 8192,  gKl + go);
        cpa16(d + 16384, gVh + go);
        cpa16(d + 24576, gVl + go);
    }
}

__global__ __launch_bounds__(256, 2) void flash_pre()
{
    __shared__ float sred[64];
    const uint32_t sb = (uint32_t)__cvta_generic_to_shared(dsm);
    const int qt = (int)gridDim.x - 1 - (int)blockIdx.x;   // longest-first
    const int h = blockIdx.y, b = blockIdx.z;
    const int tid = threadIdx.x, lane = tid & 31, wid = tid >> 5;
    const int g = lane >> 2, t = lane & 3;
    const int m8 = lane >> 3, ri = lane & 7;
    const size_t base = (size_t)(b * NHEAD + h) * TQ * DHEAD;

    // ---- Q hi/lo cp.async into stage-1 region (reused for KV later) ----
#pragma unroll
    for (int it = 0; it < 4; it++) {
        int id = tid + it * 256;
        int r = id >> 3, c = id & 7;
        uint32_t d = sb + FSTG + r * 128 + ((c ^ (r & 7)) << 4);
        size_t go = base + (size_t)(qt * 128 + r) * DHEAD + c * 8;
        cpa16(d,         gQh + go);
        cpa16(d + 16384, gQl + go);
    }
    CP_COMMIT();
    flash_issue_kv(sb, base, 0, tid); CP_COMMIT();
    CP_WAIT(1);                 // Q arrived (KV0 may still be in flight)
    __syncthreads();

    // ---- hoist Q fragments (constant across j) ----
    unsigned qh[4][4], ql[4][4];
#pragma unroll
    for (int ks = 0; ks < 4; ks++) {
        int row = wid * 16 + (m8 & 1) * 8 + ri;
        int c = 2 * ks + (m8 >> 1);
        uint32_t a = sb + FSTG + row * 128 + ((c ^ (row & 7)) << 4);
        ldsm4(qh[ks][0], qh[ks][1], qh[ks][2], qh[ks][3], a);
        ldsm4(ql[ks][0], ql[ks][1], ql[ks][2], ql[ks][3], a + 16384);
    }
    __syncthreads();            // all warps done with Q region before KV1 overwrites

    float oc[8][4];
#pragma unroll
    for (int nt = 0; nt < 8; nt++)
#pragma unroll
        for (int i = 0; i < 4; i++) oc[nt][i] = 0.f;

    float m0 = -1e30f, m1 = -1e30f, l0s = 0.f, l1s = 0.f, aa0 = 0.f, aa1 = 0.f;
    const int rowbase = qt * 128 + wid * 16;
    const int nj = 2 * qt + 2;

    for (int j = 0; j < nj; j++) {
        if (j + 1 < nj) flash_issue_kv(sb + ((j + 1) & 1) * FSTG, base, j + 1, tid);
        CP_COMMIT();
        CP_WAIT(1);
        __syncthreads();
        const uint32_t kv = sb + (j & 1) * FSTG;

        // ---- S = Q K^T ----
        float sc[8][4];
#pragma unroll
        for (int nt = 0; nt < 8; nt++)
#pragma unroll
            for (int i = 0; i < 4; i++) sc[nt][i] = 0.f;

#pragma unroll
        for (int ks = 0; ks < 4; ks++) {
#pragma unroll
            for (int ntp = 0; ntp < 4; ntp++) {
                int kr = ntp * 16 + (m8 & 1) * 8 + ri;
                int c = 2 * ks + (m8 >> 1);
                uint32_t ka = kv + kr * 128 + ((c ^ (kr & 7)) << 4);
                unsigned kh[4], kl[4];
                ldsm4(kh[0], kh[1], kh[2], kh[3], ka);
                ldsm4(kl[0], kl[1], kl[2], kl[3], ka + 8192);
                mma16(sc[2*ntp],   qh[ks], kh[0], kh[2]);
                mma16(sc[2*ntp],   ql[ks], kh[0], kh[2]);
                mma16(sc[2*ntp],   qh[ks], kl[0], kl[2]);
                mma16(sc[2*ntp+1], qh[ks], kh[1], kh[3]);
                mma16(sc[2*ntp+1], ql[ks], kh[1], kh[3]);
                mma16(sc[2*ntp+1], qh[ks], kl[1], kl[3]);
            }
        }

        // ---- scale + causal mask ----
        const bool needmask = (j * 64 + 63) > rowbase;
#pragma unroll
        for (int nt = 0; nt < 8; nt++) {
#pragma unroll
            for (int cc = 0; cc < 4; cc++) {
                float v = sc[nt][cc] * 0.125f;
                if (needmask) {
                    int col = j * 64 + nt * 8 + 2 * t + (cc & 1);
                    int row = rowbase + g + ((cc >> 1) << 3);
                    if (col > row) v = -1e30f;
                }
                sc[nt][cc] = v;
            }
        }

        // ---- online softmax + entropy ----
        float mt0 = -1e30f, mt1 = -1e30f;
#pragma unroll
        for (int nt = 0; nt < 8; nt++) {
            mt0 = fmaxf(mt0, fmaxf(sc[nt][0], sc[nt][1]));
            mt1 = fmaxf(mt1, fmaxf(sc[nt][2], sc[nt][3]));
        }
        mt0 = fmaxf(mt0, __shfl_xor_sync(0xffffffffu, mt0, 1));
        mt0 = fmaxf(mt0, __shfl_xor_sync(0xffffffffu, mt0, 2));
        mt1 = fmaxf(mt1, __shfl_xor_sync(0xffffffffu, mt1, 1));
        mt1 = fmaxf(mt1, __shfl_xor_sync(0xffffffffu, mt1, 2));

        const float mn0 = fmaxf(m0, mt0), mn1 = fmaxf(m1, mt1);
        const float ex0 = __expf(m0 - mn0), ex1 = __expf(m1 - mn1);

        float ls0 = 0.f, ls1 = 0.f, as0 = 0.f, as1 = 0.f;
#pragma unroll
        for (int nt = 0; nt < 8; nt++) {
            float s0 = sc[nt][0], s1 = sc[nt][1];
            float s2 = sc[nt][2], s3 = sc[nt][3];
            float p0 = __expf(s0 - mn0), p1 = __expf(s1 - mn0);
            float p2 = __expf(s2 - mn1), p3 = __expf(s3 - mn1);
            sc[nt][0] = p0; sc[nt][1] = p1; sc[nt][2] = p2; sc[nt][3] = p3;
            ls0 += p0 + p1;           ls1 += p2 + p3;
            as0 += p0 * s0 + p1 * s1; as1 += p2 * s2 + p3 * s3;
        }
        ls0 += __shfl_xor_sync(0xffffffffu, ls0, 1);
        ls0 += __shfl_xor_sync(0xffffffffu, ls0, 2);
        ls1 += __shfl_xor_sync(0xffffffffu, ls1, 1);
        ls1 += __shfl_xor_sync(0xffffffffu, ls1, 2);
        as0 += __shfl_xor_sync(0xffffffffu, as0, 1);
        as0 += __shfl_xor_sync(0xffffffffu, as0, 2);
        as1 += __shfl_xor_sync(0xffffffffu, as1, 1);
        as1 += __shfl_xor_sync(0xffffffffu, as1, 2);

        l0s = l0s * ex0 + ls0;  aa0 = aa0 * ex0 + as0;  m0 = mn0;
        l1s = l1s * ex1 + ls1;  aa1 = aa1 * ex1 + as1;  m1 = mn1;

#pragma unroll
        for (int nt = 0; nt < 8; nt++) {
            oc[nt][0] *= ex0; oc[nt][1] *= ex0;
            oc[nt][2] *= ex1; oc[nt][3] *= ex1;
        }

        // ---- pack P (C-frag pairs == k16 A-frags) ----
        unsigned ph0[8], pl0[8], ph1[8], pl1[8];
#pragma unroll
        for (int nt = 0; nt < 8; nt++) {
            split2(sc[nt][0], sc[nt][1], ph0[nt], pl0[nt]);
            split2(sc[nt][2], sc[nt][3], ph1[nt], pl1[nt]);
        }

        // ---- O += P @ V ----
#pragma unroll
        for (int ks = 0; ks < 4; ks++) {
            unsigned aH[4] = {ph0[2*ks], ph1[2*ks], ph0[2*ks+1], ph1[2*ks+1]};
            unsigned aL[4] = {pl0[2*ks], pl1[2*ks], pl0[2*ks+1], pl1[2*ks+1]};
#pragma unroll
            for (int ntp = 0; ntp < 4; ntp++) {
                int vr = 16 * ks + (m8 & 1) * 8 + ri;
                int c = ntp * 2 + (m8 >> 1);
                uint32_t va = kv + 16384 + vr * 128 + ((c ^ (vr & 7)) << 4);
                unsigned vh[4], vl[4];
                ldsm4t(vh[0], vh[1], vh[2], vh[3], va);
                ldsm4t(vl[0], vl[1], vl[2], vl[3], va + 8192);
                mma16(oc[2*ntp],   aH, vh[0], vh[1]);
                mma16(oc[2*ntp],   aL, vh[0], vh[1]);
                mma16(oc[2*ntp],   aH, vl[0], vl[1]);
                mma16(oc[2*ntp+1], aH, vh[2], vh[3]);
                mma16(oc[2*ntp+1], aL, vh[2], vh[3]);
                mma16(oc[2*ntp+1], aH, vl[2], vl[3]);
            }
        }
        __syncthreads();
    }

    // ---- epilogue: write yatt hi/lo planes ----
    const float inv0 = 1.f / l0s, inv1 = 1.f / l1s;
    const int trow = rowbase + g;
#pragma unroll
    for (int nt = 0; nt < 8; nt++) {
        const int col = h * DHEAD + nt * 8 + 2 * t;
        size_t idx = ((size_t)b * TQ + trow) * CDIM + col;
        unsigned hw, lw;
        split2(oc[nt][0] * inv0, oc[nt][1] * inv0, hw, lw);
        *(unsigned*)&gYh[idx] = hw; *(unsigned*)&gYl[idx] = lw;
        split2(oc[nt][2] * inv1, oc[nt][3] * inv1, hw, lw);
        *(unsigned*)&gYh[idx + 8 * CDIM] = hw; *(unsigned*)&gYl[idx + 8 * CDIM] = lw;
    }

    // ---- entropy partial ----
    if (t == 0) {
        float H = (m0 + __logf(l0s) - aa0 / l0s) + (m1 + __logf(l1s) - aa1 / l1s);
        sred[wid * 8 + g] = H;
    }
    __syncthreads();
    if (tid == 0) {
        float s = 0.f;
#pragma unroll 8
        for (int r = 0; r < 64; r++) s += sred[r];
        g_ent[((size_t)b * NHEAD + h) * NQT2 + qt] = s;
    }
}

// =====================================================================
// entropy final reduction
// =====================================================================
__global__ void ent_final_kernel(float* __restrict__ out, int out_size)
{
    __shared__ float red[256];
    int tid = threadIdx.x;
    float s = 0.f;
    for (int i = tid; i < BATCH * NHEAD * NQT2; i += 256) s += g_ent[i];
    red[tid] = s;
    __syncthreads();
    for (int st = 128; st > 0; st >>= 1) {
        if (tid < st) red[tid] += red[tid + st];
        __syncthreads();
    }
    if (tid == 0) out[out_size - 1] = red[0] / (float)NROWS;
}

// =====================================================================
// launch
// =====================================================================
extern "C" void kernel_launch(void* const* d_in, const int* in_sizes, int n_in,
                              void* d_out, int out_size)
{
    const float* x      = (const float*)d_in[0];
    const float* w_attn = (const float*)d_in[1];
    const float* w_proj = (const float*)d_in[2];
    float* out = (float*)d_out;
    (void)in_sizes; (void)n_in;

    __nv_bfloat16 *xh, *xl, *wah, *wal, *wph, *wpl, *yh, *yl;
    cudaGetSymbolAddress((void**)&xh,  gXh);  cudaGetSymbolAddress((void**)&xl,  gXl);
    cudaGetSymbolAddress((void**)&wah, gWAh); cudaGetSymbolAddress((void**)&wal, gWAl);
    cudaGetSymbolAddress((void**)&wph, gWPh); cudaGetSymbolAddress((void**)&wpl, gWPl);
    cudaGetSymbolAddress((void**)&yh,  gYh);  cudaGetSymbolAddress((void**)&yl,  gYl);

    const int GEMM_SMEM  = 3 * GSTG;   // 98304
    const int FLASH_SMEM = 2 * FSTG;   // 65536
    cudaFuncSetAttribute(gemm_pre,
                         cudaFuncAttributeMaxDynamicSharedMemorySize, GEMM_SMEM);
    cudaFuncSetAttribute(flash_pre,
                         cudaFuncAttributeMaxDynamicSharedMemorySize, FLASH_SMEM);

    // 0) split inputs
    {
        int n4x = BATCH * TQ * CDIM / 4;
        split_kernel<<<(n4x + 255) / 256, 256>>>(x, xh, xl, n4x);
        int n4a = CDIM * C3 / 4;
        split_kernel<<<(n4a + 255) / 256, 256>>>(w_attn, wah, wal, n4a);
        int n4p = CDIM * CDIM / 4;
        split_kernel<<<(n4p + 255) / 256, 256>>>(w_proj, wph, wpl, n4p);
    }
    // 1) qkv = x @ w_attn  -> split qkv planes (mode 1)
    {
        dim3 grid(C3 / 128, (BATCH * TQ) / 128);
        gemm_pre<<<grid, 256, GEMM_SMEM>>>(xh, xl, wah, wal, nullptr,
                                           BATCH * TQ, C3, CDIM, 1);
    }
    // 2) flash attention + entropy partials -> gY planes
    {
        dim3 grid(NQT2, NHEAD, BATCH);
        flash_pre<<<grid, 256, FLASH_SMEM>>>();
    }
    // 3) y = yatt @ w_proj -> d_out (mode 0)
    {
        dim3 grid(CDIM / 128, (BATCH * TQ) / 128);
        gemm_pre<<<grid, 256, GEMM_SMEM>>>(yh, yl, wph, wpl, out,
                                           BATCH * TQ, CDIM, CDIM, 0);
    }
    // 4) entropy scalar
    ent_final_kernel<<<1, 256>>>(out, out_size);
}